// round 9
// baseline (speedup 1.0000x reference)
#include <cuda_runtime.h>
#include <math.h>

static constexpr int NB = 128;     // batch
static constexpr int SL = 256;     // seq len
static constexpr int QL = 8;       // query len
static constexpr int ED = 300;     // embed dim
static constexpr int HD = 300;     // hidden dim
static constexpr int GW = 1200;    // 4*HD gate width
static constexpr int MS = NB * SL; // 32768
static constexpr int MQ = NB * QL; // 1024
static constexpr float EPSN = 1e-12f;

// ---------------- static device scratch (no runtime allocation) ----------------
__device__ float d_Gf[MS * GW];        // input-proj gates, seqs forward  (incl. biases)
__device__ float d_Gb[MS * GW];        // seqs backward
__device__ float d_Gqf[MQ * GW];       // queries forward
__device__ float d_Gqb[MQ * GW];       // queries backward
__device__ float d_Hcat[MS * 2 * HD];  // [N, L, 2H] concat(hf, hb)
__device__ float d_HcatQ[MQ * 2 * HD];
__device__ float d_h[2 * 2 * NB * HD]; // [dir][parity][N*H] ping-pong hidden
__device__ float d_c[2 * NB * HD];     // [dir][N*H] cell (seqs)
__device__ float d_hq[2 * 2 * NB * HD];
__device__ float d_cq[2 * NB * HD];    // cell (queries)
__device__ float d_hs[MS * HD];        // encoded seq states
__device__ float d_qenc[MQ * HD];      // encoded query states
__device__ float d_tmp[MS * HD];       // tanh(hs@Wa^T+ba); later reused as P = hs@Wf
__device__ float d_tmpq[MQ * HD];
__device__ float d_s[MS];              // attention logits (seqs)
__device__ float d_sq[MQ];             // attention logits (queries)
__device__ float d_qv[NB * HD];        // pooled query vec
__device__ float d_qp[NB * HD];        // qv @ Wf
__device__ float d_qn[NB * HD];        // normalized

// ---------------- init ----------------
__global__ void init_state() {
    int i = blockIdx.x * blockDim.x + threadIdx.x;
    if (i < 2 * 2 * NB * HD) { d_h[i] = 0.f; d_hq[i] = 0.f; }
    if (i < 2 * NB * HD)     { d_c[i] = 0.f; d_cq[i] = 0.f; }
}

// ---------------- gathered input-projection GEMM (double-buffered) ----------------
// G[m, j] = sum_e emb[tok[m], e] * W[j, e] + b1[j] + b2[j]    (M x 1200, K=300)
__global__ void __launch_bounds__(256)
proj_gemm(const int* __restrict__ tok, const float* __restrict__ emb,
          const float* __restrict__ W, const float* __restrict__ b1,
          const float* __restrict__ b2, float* __restrict__ G, int M) {
    __shared__ __align__(16) float As[2][8][128];
    __shared__ __align__(16) float Bs[2][8][128];
    int tid = threadIdx.x;
    int m0 = blockIdx.y * 128, n0 = blockIdx.x * 128;
    int tx = tid % 16, ty = tid / 16;
    int am = tid >> 1, akq = (tid & 1) * 4;
    int arow = m0 + am;
    const float* aptr = emb + (size_t)((arow < M) ? tok[arow] : 0) * ED;
    int bcol = n0 + am;
    float acc[8][8];
#pragma unroll
    for (int i = 0; i < 8; i++)
#pragma unroll
        for (int j = 0; j < 8; j++) acc[i][j] = 0.f;

    float ra[4], rbv[4];
    const int nP = (ED + 7) / 8;  // 38

#pragma unroll
    for (int j = 0; j < 4; j++) {
        int kk = akq + j;
        ra[j]  = (arow < M && kk < ED) ? aptr[kk] : 0.f;
        rbv[j] = (bcol < GW && kk < ED) ? W[(size_t)bcol * ED + kk] : 0.f;
    }
#pragma unroll
    for (int j = 0; j < 4; j++) { As[0][akq + j][am] = ra[j]; Bs[0][akq + j][am] = rbv[j]; }
    __syncthreads();

    for (int p = 0; p < nP; p++) {
        if (p + 1 < nP) {
            int k0 = (p + 1) * 8;
#pragma unroll
            for (int j = 0; j < 4; j++) {
                int kk = k0 + akq + j;
                ra[j]  = (arow < M && kk < ED) ? aptr[kk] : 0.f;
                rbv[j] = (bcol < GW && kk < ED) ? W[(size_t)bcol * ED + kk] : 0.f;
            }
        }
        int b = p & 1;
#pragma unroll
        for (int k = 0; k < 8; k++) {
            float4 a0 = *(const float4*)&As[b][k][ty * 8];
            float4 a1 = *(const float4*)&As[b][k][ty * 8 + 4];
            float4 c0 = *(const float4*)&Bs[b][k][tx * 8];
            float4 c1 = *(const float4*)&Bs[b][k][tx * 8 + 4];
            float av8[8] = {a0.x, a0.y, a0.z, a0.w, a1.x, a1.y, a1.z, a1.w};
            float bv8[8] = {c0.x, c0.y, c0.z, c0.w, c1.x, c1.y, c1.z, c1.w};
#pragma unroll
            for (int i = 0; i < 8; i++)
#pragma unroll
                for (int j = 0; j < 8; j++) acc[i][j] += av8[i] * bv8[j];
        }
        if (p + 1 < nP) {
            int nb = (p + 1) & 1;
#pragma unroll
            for (int j = 0; j < 4; j++) { As[nb][akq + j][am] = ra[j]; Bs[nb][akq + j][am] = rbv[j]; }
            __syncthreads();
        }
    }
#pragma unroll
    for (int i = 0; i < 8; i++) {
        int row = m0 + ty * 8 + i;
        if (row < M) {
#pragma unroll
            for (int j = 0; j < 8; j++) {
                int col = n0 + tx * 8 + j;
                if (col < GW) G[(size_t)row * GW + col] = acc[i][j] + b1[col] + b2[col];
            }
        }
    }
}

// ---------------- generic SGEMM (double-buffered): C = A @ op(B) (+bias)(+tanh) ----
__global__ void __launch_bounds__(256)
gemm_k(const float* __restrict__ A, const float* __restrict__ B,
       const float* __restrict__ bias, float* __restrict__ C,
       int M, int N, int K, int transB, int act) {
    __shared__ __align__(16) float As[2][8][128];
    __shared__ __align__(16) float Bs[2][8][128];
    int tid = threadIdx.x;
    int m0 = blockIdx.y * 128, n0 = blockIdx.x * 128;
    int tx = tid % 16, ty = tid / 16;
    int am = tid >> 1, akq = (tid & 1) * 4;
    int arow = m0 + am, bcol = n0 + am;
    float acc[8][8];
#pragma unroll
    for (int i = 0; i < 8; i++)
#pragma unroll
        for (int j = 0; j < 8; j++) acc[i][j] = 0.f;

    float ra[4], rbv[4];
    const int nP = (K + 7) / 8;

    auto loadP = [&](int k0) {
#pragma unroll
        for (int j = 0; j < 4; j++) {
            int kk = k0 + akq + j;
            ra[j] = (arow < M && kk < K) ? A[(size_t)arow * K + kk] : 0.f;
        }
        if (transB) {
#pragma unroll
            for (int j = 0; j < 4; j++) {
                int kk = k0 + akq + j;
                rbv[j] = (bcol < N && kk < K) ? B[(size_t)bcol * K + kk] : 0.f;
            }
        } else {
#pragma unroll
            for (int i = 0; i < 4; i++) {
                int idx = tid + i * 256;
                int k = idx >> 7, j = idx & 127;
                rbv[i] = (k0 + k < K && n0 + j < N) ? B[(size_t)(k0 + k) * N + n0 + j] : 0.f;
            }
        }
    };
    auto storeP = [&](int b) {
#pragma unroll
        for (int j = 0; j < 4; j++) As[b][akq + j][am] = ra[j];
        if (transB) {
#pragma unroll
            for (int j = 0; j < 4; j++) Bs[b][akq + j][am] = rbv[j];
        } else {
#pragma unroll
            for (int i = 0; i < 4; i++) {
                int idx = tid + i * 256;
                Bs[b][idx >> 7][idx & 127] = rbv[i];
            }
        }
    };

    loadP(0); storeP(0);
    __syncthreads();

    for (int p = 0; p < nP; p++) {
        if (p + 1 < nP) loadP((p + 1) * 8);
        int b = p & 1;
#pragma unroll
        for (int k = 0; k < 8; k++) {
            float4 a0 = *(const float4*)&As[b][k][ty * 8];
            float4 a1 = *(const float4*)&As[b][k][ty * 8 + 4];
            float4 c0 = *(const float4*)&Bs[b][k][tx * 8];
            float4 c1 = *(const float4*)&Bs[b][k][tx * 8 + 4];
            float av8[8] = {a0.x, a0.y, a0.z, a0.w, a1.x, a1.y, a1.z, a1.w};
            float bv8[8] = {c0.x, c0.y, c0.z, c0.w, c1.x, c1.y, c1.z, c1.w};
#pragma unroll
            for (int i = 0; i < 8; i++)
#pragma unroll
                for (int j = 0; j < 8; j++) acc[i][j] += av8[i] * bv8[j];
        }
        if (p + 1 < nP) { storeP((p + 1) & 1); __syncthreads(); }
    }
#pragma unroll
    for (int i = 0; i < 8; i++) {
        int row = m0 + ty * 8 + i;
        if (row < M) {
#pragma unroll
            for (int j = 0; j < 8; j++) {
                int col = n0 + tx * 8 + j;
                if (col < N) {
                    float v = acc[i][j] + (bias ? bias[col] : 0.f);
                    if (act) v = tanhf(v);
                    C[(size_t)row * N + col] = v;
                }
            }
        }
    }
}

// ---------------- fused LSTM recurrence step v5 (256 threads: 2 warps/SMSP) -----
// grid (10, 8, 2) = 160 CTAs x 256 threads. CTA = (4 gates x 32 units) x 16 rows.
// Thread = 4 cols (one gate) x 2 rows -> 8 FFMA per k vs 1 LDS.128 + 2 LDS.32.
// 2 warps per SMSP keep the FMA pipe at its rt=2 floor and absorb stalls.
// Whh streamed in 20-k double-buffered panels (load split: 128 cols x 2 k-halves).
__device__ __forceinline__ float sigm(float x) { return 1.f / (1.f + expf(-x)); }

__global__ void __launch_bounds__(256)
lstm_step(const float* __restrict__ WhhF, const float* __restrict__ WhhB,
          int t, int Lcur, int isq) {
    const int tid = threadIdx.x;
    const int tx = tid & 31;   // col-group: cols tx*4..+3 (gate = tx>>3)
    const int ty = tid >> 5;   // 0..7 -> rows ty, ty+8
    const int ub = blockIdx.x, rbk = blockIdx.y, dir = blockIdx.z;
    const int u0 = ub * 32, n0 = rbk * 16;

    const float* __restrict__ Whh = dir ? WhhB : WhhF;
    const float* __restrict__ G = isq ? (dir ? d_Gqb : d_Gqf)
                                      : (dir ? d_Gb : d_Gf);
    float* hbase = isq ? d_hq : d_h;
    float* cbuf = (isq ? d_cq : d_c) + dir * (NB * HD);
    const float* hp = hbase + (dir * 2 + (t & 1)) * (NB * HD);
    float* hn = hbase + (dir * 2 + ((t + 1) & 1)) * (NB * HD);
    float* Hc = isq ? d_HcatQ : d_Hcat;
    const int tpos = dir ? (Lcur - 1 - t) : t;

    __shared__ __align__(16) float h_s[16][304];     // h_prev rows
    __shared__ __align__(16) float Ws[2][20][128];   // double-buffered k-panels
    __shared__ __align__(16) float gs[16][128];      // staged gates

    // --- acc init: this step's input-proj gates (biases included) ---
    const int gate = tx >> 3;
    const int un = u0 + (tx & 7) * 4;
    const bool uval = (un < HD);
    float acc[2][4];
#pragma unroll
    for (int j = 0; j < 2; j++) {
        if (uval) {
            int n = n0 + ty + 8 * j;
            float4 v = *(const float4*)(G + ((size_t)n * Lcur + tpos) * GW
                                          + gate * HD + un);
            acc[j][0] = v.x; acc[j][1] = v.y; acc[j][2] = v.z; acc[j][3] = v.w;
        } else {
            acc[j][0] = acc[j][1] = acc[j][2] = acc[j][3] = 0.f;
        }
    }

    // --- h_prev staging: LDG phase (full MLP) then STS phase ---
    float4 hreg[5];
#pragma unroll
    for (int q = 0; q < 5; q++) {
        int i = tid + q * 256;
        if (i < 1200) {
            int r = i / 75, c = i - r * 75;
            hreg[q] = *((const float4*)(hp + (size_t)(n0 + r) * HD) + c);
        }
    }
#pragma unroll
    for (int q = 0; q < 5; q++) {
        int i = tid + q * 256;
        if (i < 1200) {
            int r = i / 75, c = i - r * 75;
            *((float4*)&h_s[r][0] + c) = hreg[q];
        }
    }

    // --- Whh panel pipeline (20 k per panel, 15 panels, double-buffered) ---
    // loader: col lc = tid&127 (gate = lc>>5, unit = u0+(lc&31)); half = tid>>7
    // half 0 -> kk 0..11 (3 float4), half 1 -> kk 12..19 (2 float4)
    const int lc = tid & 127;
    const int half = tid >> 7;
    const int lrow = (lc >> 5) * HD + u0 + (lc & 31);
    const bool lval = (u0 + (lc & 31)) < HD;
    const int qb = half ? 3 : 0;           // first float4 index
    const int qn = half ? 2 : 3;           // number of float4s
    float4 pre[3];

    // prologue: panel 0
    if (lval) {
        const float* src = Whh + (size_t)lrow * HD;
#pragma unroll
        for (int q = 0; q < 3; q++)
            if (q < qn) pre[q] = ((const float4*)src)[qb + q];
#pragma unroll
        for (int q = 0; q < 3; q++) {
            if (q < qn) {
                int kk = (qb + q) * 4;
                Ws[0][kk + 0][lc] = pre[q].x;
                Ws[0][kk + 1][lc] = pre[q].y;
                Ws[0][kk + 2][lc] = pre[q].z;
                Ws[0][kk + 3][lc] = pre[q].w;
            }
        }
    } else {
#pragma unroll
        for (int q = 0; q < 3; q++) {
            if (q < qn) {
                int kk = (qb + q) * 4;
                Ws[0][kk + 0][lc] = 0.f; Ws[0][kk + 1][lc] = 0.f;
                Ws[0][kk + 2][lc] = 0.f; Ws[0][kk + 3][lc] = 0.f;
            }
        }
    }
    __syncthreads();  // panel 0 + h_s visible

    for (int p = 0; p < 15; p++) {
        if (p + 1 < 15 && lval) {
            const float* src = Whh + (size_t)lrow * HD + (p + 1) * 20;
#pragma unroll
            for (int q = 0; q < 3; q++)
                if (q < qn) pre[q] = ((const float4*)src)[qb + q];
        }
        const int b = p & 1, k0 = p * 20;
#pragma unroll
        for (int kk = 0; kk < 20; kk++) {
            float4 w = *(const float4*)&Ws[b][kk][tx * 4];
            float h0 = h_s[ty][k0 + kk];
            float h1 = h_s[ty + 8][k0 + kk];
            acc[0][0] += h0 * w.x; acc[0][1] += h0 * w.y;
            acc[0][2] += h0 * w.z; acc[0][3] += h0 * w.w;
            acc[1][0] += h1 * w.x; acc[1][1] += h1 * w.y;
            acc[1][2] += h1 * w.z; acc[1][3] += h1 * w.w;
        }
        if (p + 1 < 15) {
            const int nb = (p + 1) & 1;
            if (lval) {
#pragma unroll
                for (int q = 0; q < 3; q++) {
                    if (q < qn) {
                        int kk = (qb + q) * 4;
                        Ws[nb][kk + 0][lc] = pre[q].x;
                        Ws[nb][kk + 1][lc] = pre[q].y;
                        Ws[nb][kk + 2][lc] = pre[q].z;
                        Ws[nb][kk + 3][lc] = pre[q].w;
                    }
                }
            } else {
#pragma unroll
                for (int q = 0; q < 3; q++) {
                    if (q < qn) {
                        int kk = (qb + q) * 4;
                        Ws[nb][kk + 0][lc] = 0.f; Ws[nb][kk + 1][lc] = 0.f;
                        Ws[nb][kk + 2][lc] = 0.f; Ws[nb][kk + 3][lc] = 0.f;
                    }
                }
            }
            __syncthreads();
        }
    }

    // regroup gates through smem (thread holds 4 cols of ONE gate x 2 rows)
#pragma unroll
    for (int j = 0; j < 2; j++) {
        int r = ty + 8 * j;
        *(float4*)&gs[r][tx * 4] = make_float4(acc[j][0], acc[j][1],
                                               acc[j][2], acc[j][3]);
    }
    __syncthreads();

    // cell update: 2 (unit,row) pairs per thread
    for (int p = tid; p < 512; p += 256) {
        int ulane = p & 31, r = p >> 5;
        int u = u0 + ulane;
        if (u < HD) {
            int n = n0 + r;
            float gi = gs[r][ulane];
            float gf = gs[r][32 + ulane];
            float gg = gs[r][64 + ulane];
            float go = gs[r][96 + ulane];
            float cold = cbuf[n * HD + u];
            float cn = sigm(gf) * cold + sigm(gi) * tanhf(gg);
            float hv = sigm(go) * tanhf(cn);
            cbuf[n * HD + u] = cn;
            hn[n * HD + u] = hv;
            Hc[((size_t)n * Lcur + tpos) * (2 * HD) + dir * HD + u] = hv;
        }
    }
}

// ---------------- attention dot: s[m] = dot(X[m,:], av) ----------------
__global__ void att_dot(const float* __restrict__ X, const float* __restrict__ av,
                        float* __restrict__ out, int M) {
    int w = (blockIdx.x * blockDim.x + threadIdx.x) >> 5;
    int lane = threadIdx.x & 31;
    if (w >= M) return;
    const float* x = X + (size_t)w * HD;
    float a = 0.f;
    for (int d = lane; d < HD; d += 32) a += x[d] * av[d];
#pragma unroll
    for (int o = 16; o; o >>= 1) a += __shfl_down_sync(0xffffffffu, a, o);
    if (lane == 0) out[w] = a;
}

// ---------------- query softmax pool ----------------
__global__ void qpool_k() {
    int n = blockIdx.x, tid = threadIdx.x;  // 128 threads
    __shared__ float sc[QL];
    if (tid < QL) sc[tid] = d_sq[n * QL + tid];
    __syncthreads();
    float mx = -1e30f;
#pragma unroll
    for (int l = 0; l < QL; l++) mx = fmaxf(mx, sc[l]);
    float e[QL], sum = 0.f;
#pragma unroll
    for (int l = 0; l < QL; l++) { e[l] = expf(sc[l] - mx); sum += e[l]; }
    float inv = 1.f / sum;
    for (int d = tid; d < HD; d += 128) {
        float a = 0.f;
#pragma unroll
        for (int l = 0; l < QL; l++) a += e[l] * d_qenc[(n * QL + l) * HD + d];
        d_qv[n * HD + d] = a * inv;
    }
}

// ---------------- normalize query: qn = qp / max(||qp||, eps) ----------------
__global__ void qnorm_k() {
    int n = blockIdx.x, tid = threadIdx.x;  // 128 threads
    __shared__ float red[128];
    float ss = 0.f;
    for (int d = tid; d < HD; d += 128) { float v = d_qp[n * HD + d]; ss += v * v; }
    red[tid] = ss;
    __syncthreads();
    for (int s = 64; s; s >>= 1) { if (tid < s) red[tid] += red[tid + s]; __syncthreads(); }
    float inv = 1.f / fmaxf(sqrtf(red[0]), EPSN);
    for (int d = tid; d < HD; d += 128) d_qn[n * HD + d] = d_qp[n * HD + d] * inv;
}

// ---------------- final: sliding-window combos + cosines + mix ----------------
__global__ void final_k(const float* __restrict__ sw, const float* __restrict__ P,
                        float* __restrict__ out) {
    int w = (blockIdx.x * blockDim.x + threadIdx.x) >> 5;
    int lane = threadIdx.x & 31;
    if (w >= MS) return;
    int n = w >> 8, l = w & 255;
    int ln = (l + 1 < SL) ? l + 1 : SL - 1;
    int lp = (l > 0) ? l - 1 : 0;
    float sl = d_s[n * SL + l];
    float sn = d_s[n * SL + ln];
    float sp = d_s[n * SL + lp];
    float m1 = fmaxf(sl, sn);
    float e0 = expf(sl - m1), e1 = expf(sn - m1);
    float wf0 = e0 / (e0 + e1), wf1 = 1.f - wf0;
    float m2 = fmaxf(sp, sl);
    float f0 = expf(sp - m2), f1 = expf(sl - m2);
    float wb0 = f0 / (f0 + f1), wb1 = 1.f - wb0;

    const float* Pl = P + (size_t)(n * SL + l) * HD;
    const float* Pn = P + (size_t)(n * SL + ln) * HD;
    const float* Pp = P + (size_t)(n * SL + lp) * HD;
    const float* q = d_qn + n * HD;

    float dpq = 0.f, dpp = 0.f, duq = 0.f, duu = 0.f, dvq = 0.f, dvv = 0.f;
    for (int d = lane; d < HD; d += 32) {
        float p = Pl[d], pn = Pn[d], pp = Pp[d], qd = q[d];
        float u = wf0 * p + wf1 * pn;
        float v = wb0 * pp + wb1 * p;
        dpq += p * qd; dpp += p * p;
        duq += u * qd; duu += u * u;
        dvq += v * qd; dvv += v * v;
    }
#pragma unroll
    for (int o = 16; o; o >>= 1) {
        dpq += __shfl_down_sync(0xffffffffu, dpq, o);
        dpp += __shfl_down_sync(0xffffffffu, dpp, o);
        duq += __shfl_down_sync(0xffffffffu, duq, o);
        duu += __shfl_down_sync(0xffffffffu, duu, o);
        dvq += __shfl_down_sync(0xffffffffu, dvq, o);
        dvv += __shfl_down_sync(0xffffffffu, dvv, o);
    }
    if (lane == 0) {
        float c1 = dpq / fmaxf(sqrtf(dpp), EPSN);
        float c2 = duq / fmaxf(sqrtf(duu), EPSN);
        float c3 = dvq / fmaxf(sqrtf(dvv), EPSN);
        out[w] = c1 * sw[0] + c2 * sw[1] + c3 * sw[2];
    }
}

// ---------------- launch ----------------
extern "C" void kernel_launch(void* const* d_in, const int* in_sizes, int n_in,
                              void* d_out, int out_size) {
    const int*   seqs = (const int*)d_in[0];
    const int*   quer = (const int*)d_in[1];
    const float* emb  = (const float*)d_in[2];
    const float* WihF = (const float*)d_in[3];
    const float* WhhF = (const float*)d_in[4];
    const float* bihF = (const float*)d_in[5];
    const float* bhhF = (const float*)d_in[6];
    const float* WihB = (const float*)d_in[7];
    const float* WhhB = (const float*)d_in[8];
    const float* bihB = (const float*)d_in[9];
    const float* bhhB = (const float*)d_in[10];
    const float* Wc   = (const float*)d_in[11];
    const float* bc   = (const float*)d_in[12];
    const float* Wa   = (const float*)d_in[13];
    const float* ba   = (const float*)d_in[14];
    const float* av   = (const float*)d_in[15];
    const float* Wf   = (const float*)d_in[16];
    const float* sw   = (const float*)d_in[17];

    void* p;
    cudaGetSymbolAddress(&p, d_Gf);    float* pGf    = (float*)p;
    cudaGetSymbolAddress(&p, d_Gb);    float* pGb    = (float*)p;
    cudaGetSymbolAddress(&p, d_Gqf);   float* pGqf   = (float*)p;
    cudaGetSymbolAddress(&p, d_Gqb);   float* pGqb   = (float*)p;
    cudaGetSymbolAddress(&p, d_Hcat);  float* pHcat  = (float*)p;
    cudaGetSymbolAddress(&p, d_HcatQ); float* pHcatQ = (float*)p;
    cudaGetSymbolAddress(&p, d_hs);    float* phs    = (float*)p;
    cudaGetSymbolAddress(&p, d_qenc);  float* pqenc  = (float*)p;
    cudaGetSymbolAddress(&p, d_tmp);   float* ptmp   = (float*)p;  // doubles as P
    cudaGetSymbolAddress(&p, d_tmpq);  float* ptmpq  = (float*)p;
    cudaGetSymbolAddress(&p, d_s);     float* ps     = (float*)p;
    cudaGetSymbolAddress(&p, d_sq);    float* psq    = (float*)p;
    cudaGetSymbolAddress(&p, d_qv);    float* pqv    = (float*)p;
    cudaGetSymbolAddress(&p, d_qp);    float* pqp    = (float*)p;

    init_state<<<600, 256>>>();

    // input projections (gather + GEMM + both biases)
    dim3 gp(10, 256);
    proj_gemm<<<gp, 256>>>(seqs, emb, WihF, bihF, bhhF, pGf, MS);
    proj_gemm<<<gp, 256>>>(seqs, emb, WihB, bihB, bhhB, pGb, MS);
    dim3 gpq(10, 8);
    proj_gemm<<<gpq, 256>>>(quer, emb, WihF, bihF, bhhF, pGqf, MQ);
    proj_gemm<<<gpq, 256>>>(quer, emb, WihB, bihB, bhhB, pGqb, MQ);

    // recurrences: one launch per timestep, both dirs (proven-safe structure)
    dim3 gl(10, 8, 2);
    for (int t = 0; t < SL; t++) lstm_step<<<gl, 256>>>(WhhF, WhhB, t, SL, 0);
    for (int t = 0; t < QL; t++) lstm_step<<<gl, 256>>>(WhhF, WhhB, t, QL, 1);

    // combine directions: hs = Hcat @ Wc^T + bc
    gemm_k<<<dim3(3, 256), 256>>>(pHcat, Wc, bc, phs, MS, HD, 2 * HD, 1, 0);
    gemm_k<<<dim3(3, 8), 256>>>(pHcatQ, Wc, bc, pqenc, MQ, HD, 2 * HD, 1, 0);

    // attention logits: tanh(X @ Wa^T + ba) . att_vec
    gemm_k<<<dim3(3, 256), 256>>>(phs, Wa, ba, ptmp, MS, HD, HD, 1, 1);
    gemm_k<<<dim3(3, 8), 256>>>(pqenc, Wa, ba, ptmpq, MQ, HD, HD, 1, 1);
    att_dot<<<MS / 8, 256>>>(ptmp, av, ps, MS);
    att_dot<<<MQ / 8, 256>>>(ptmpq, av, psq, MQ);

    // pooled, projected, normalized query
    qpool_k<<<NB, 128>>>();
    gemm_k<<<dim3(3, 1), 256>>>(pqv, Wf, nullptr, pqp, NB, HD, HD, 0, 0);
    qnorm_k<<<NB, 128>>>();

    // P = hs @ Wf  (fwd/bwd combos are linear in hs, so one projection suffices)
    gemm_k<<<dim3(3, 256), 256>>>(phs, Wf, nullptr, ptmp, MS, HD, HD, 0, 0);

    final_k<<<MS / 8, 256>>>(sw, ptmp, (float*)d_out);
}

// round 11
// speedup vs baseline: 1.1705x; 1.1705x over previous
#include <cuda_runtime.h>
#include <math.h>

static constexpr int NB = 128;     // batch
static constexpr int SL = 256;     // seq len
static constexpr int QL = 8;       // query len
static constexpr int ED = 300;     // embed dim
static constexpr int HD = 300;     // hidden dim
static constexpr int GW = 1200;    // 4*HD gate width
static constexpr int MS = NB * SL; // 32768
static constexpr int MQ = NB * QL; // 1024
static constexpr float EPSN = 1e-12f;

// ---------------- static device scratch (no runtime allocation) ----------------
__device__ float d_Gf[MS * GW];        // input-proj gates, seqs forward  (incl. biases)
__device__ float d_Gb[MS * GW];        // seqs backward
__device__ float d_Gqf[MQ * GW];       // queries forward
__device__ float d_Gqb[MQ * GW];       // queries backward
__device__ float d_Hcat[MS * 2 * HD];  // [N, L, 2H] concat(hf, hb)
__device__ float d_HcatQ[MQ * 2 * HD];
__device__ float d_h[2 * 2 * NB * HD]; // [dir][parity][N*H] ping-pong hidden
__device__ float d_c[2 * NB * HD];     // [dir][N*H] cell (seqs)
__device__ float d_hq[2 * 2 * NB * HD];
__device__ float d_cq[2 * NB * HD];    // cell (queries)
__device__ float d_hs[MS * HD];        // encoded seq states
__device__ float d_qenc[MQ * HD];      // encoded query states
__device__ float d_tmp[MS * HD];       // tanh(hs@Wa^T+ba); later reused as P = hs@Wf
__device__ float d_tmpq[MQ * HD];
__device__ float d_s[MS];              // attention logits (seqs)
__device__ float d_sq[MQ];             // attention logits (queries)
__device__ float d_qv[NB * HD];        // pooled query vec
__device__ float d_qp[NB * HD];        // qv @ Wf
__device__ float d_qn[NB * HD];        // normalized

// ---------------- init ----------------
__global__ void init_state() {
    int i = blockIdx.x * blockDim.x + threadIdx.x;
    if (i < 2 * 2 * NB * HD) { d_h[i] = 0.f; d_hq[i] = 0.f; }
    if (i < 2 * NB * HD)     { d_c[i] = 0.f; d_cq[i] = 0.f; }
}

// ---------------- gathered input-projection GEMM (double-buffered, 2 CTA/SM) ----
// G[m, j] = sum_e emb[tok[m], e] * W[j, e] + b1[j] + b2[j]    (M x 1200, K=300)
__global__ void __launch_bounds__(256, 2)
proj_gemm(const int* __restrict__ tok, const float* __restrict__ emb,
          const float* __restrict__ W, const float* __restrict__ b1,
          const float* __restrict__ b2, float* __restrict__ G, int M) {
    __shared__ __align__(16) float As[2][8][128];
    __shared__ __align__(16) float Bs[2][8][128];
    int tid = threadIdx.x;
    int m0 = blockIdx.y * 128, n0 = blockIdx.x * 128;
    int tx = tid % 16, ty = tid / 16;
    int am = tid >> 1, akq = (tid & 1) * 4;
    int arow = m0 + am;
    const float* aptr = emb + (size_t)((arow < M) ? tok[arow] : 0) * ED;
    int bcol = n0 + am;
    float acc[8][8];
#pragma unroll
    for (int i = 0; i < 8; i++)
#pragma unroll
        for (int j = 0; j < 8; j++) acc[i][j] = 0.f;

    float ra[4], rbv[4];
    const int nP = (ED + 7) / 8;  // 38

#pragma unroll
    for (int j = 0; j < 4; j++) {
        int kk = akq + j;
        ra[j]  = (arow < M && kk < ED) ? aptr[kk] : 0.f;
        rbv[j] = (bcol < GW && kk < ED) ? W[(size_t)bcol * ED + kk] : 0.f;
    }
#pragma unroll
    for (int j = 0; j < 4; j++) { As[0][akq + j][am] = ra[j]; Bs[0][akq + j][am] = rbv[j]; }
    __syncthreads();

    for (int p = 0; p < nP; p++) {
        if (p + 1 < nP) {
            int k0 = (p + 1) * 8;
#pragma unroll
            for (int j = 0; j < 4; j++) {
                int kk = k0 + akq + j;
                ra[j]  = (arow < M && kk < ED) ? aptr[kk] : 0.f;
                rbv[j] = (bcol < GW && kk < ED) ? W[(size_t)bcol * ED + kk] : 0.f;
            }
        }
        int b = p & 1;
#pragma unroll
        for (int k = 0; k < 8; k++) {
            float4 a0 = *(const float4*)&As[b][k][ty * 8];
            float4 a1 = *(const float4*)&As[b][k][ty * 8 + 4];
            float4 c0 = *(const float4*)&Bs[b][k][tx * 8];
            float4 c1 = *(const float4*)&Bs[b][k][tx * 8 + 4];
            float av8[8] = {a0.x, a0.y, a0.z, a0.w, a1.x, a1.y, a1.z, a1.w};
            float bv8[8] = {c0.x, c0.y, c0.z, c0.w, c1.x, c1.y, c1.z, c1.w};
#pragma unroll
            for (int i = 0; i < 8; i++)
#pragma unroll
                for (int j = 0; j < 8; j++) acc[i][j] += av8[i] * bv8[j];
        }
        if (p + 1 < nP) {
            int nb = (p + 1) & 1;
#pragma unroll
            for (int j = 0; j < 4; j++) { As[nb][akq + j][am] = ra[j]; Bs[nb][akq + j][am] = rbv[j]; }
            __syncthreads();
        }
    }
#pragma unroll
    for (int i = 0; i < 8; i++) {
        int row = m0 + ty * 8 + i;
        if (row < M) {
#pragma unroll
            for (int j = 0; j < 8; j++) {
                int col = n0 + tx * 8 + j;
                if (col < GW) G[(size_t)row * GW + col] = acc[i][j] + b1[col] + b2[col];
            }
        }
    }
}

// ---------------- generic SGEMM (double-buffered, 2 CTA/SM) ----------------
__global__ void __launch_bounds__(256, 2)
gemm_k(const float* __restrict__ A, const float* __restrict__ B,
       const float* __restrict__ bias, float* __restrict__ C,
       int M, int N, int K, int transB, int act) {
    __shared__ __align__(16) float As[2][8][128];
    __shared__ __align__(16) float Bs[2][8][128];
    int tid = threadIdx.x;
    int m0 = blockIdx.y * 128, n0 = blockIdx.x * 128;
    int tx = tid % 16, ty = tid / 16;
    int am = tid >> 1, akq = (tid & 1) * 4;
    int arow = m0 + am, bcol = n0 + am;
    float acc[8][8];
#pragma unroll
    for (int i = 0; i < 8; i++)
#pragma unroll
        for (int j = 0; j < 8; j++) acc[i][j] = 0.f;

    float ra[4], rbv[4];
    const int nP = (K + 7) / 8;

    auto loadP = [&](int k0) {
#pragma unroll
        for (int j = 0; j < 4; j++) {
            int kk = k0 + akq + j;
            ra[j] = (arow < M && kk < K) ? A[(size_t)arow * K + kk] : 0.f;
        }
        if (transB) {
#pragma unroll
            for (int j = 0; j < 4; j++) {
                int kk = k0 + akq + j;
                rbv[j] = (bcol < N && kk < K) ? B[(size_t)bcol * K + kk] : 0.f;
            }
        } else {
#pragma unroll
            for (int i = 0; i < 4; i++) {
                int idx = tid + i * 256;
                int k = idx >> 7, j = idx & 127;
                rbv[i] = (k0 + k < K && n0 + j < N) ? B[(size_t)(k0 + k) * N + n0 + j] : 0.f;
            }
        }
    };
    auto storeP = [&](int b) {
#pragma unroll
        for (int j = 0; j < 4; j++) As[b][akq + j][am] = ra[j];
        if (transB) {
#pragma unroll
            for (int j = 0; j < 4; j++) Bs[b][akq + j][am] = rbv[j];
        } else {
#pragma unroll
            for (int i = 0; i < 4; i++) {
                int idx = tid + i * 256;
                Bs[b][idx >> 7][idx & 127] = rbv[i];
            }
        }
    };

    loadP(0); storeP(0);
    __syncthreads();

    for (int p = 0; p < nP; p++) {
        if (p + 1 < nP) loadP((p + 1) * 8);
        int b = p & 1;
#pragma unroll
        for (int k = 0; k < 8; k++) {
            float4 a0 = *(const float4*)&As[b][k][ty * 8];
            float4 a1 = *(const float4*)&As[b][k][ty * 8 + 4];
            float4 c0 = *(const float4*)&Bs[b][k][tx * 8];
            float4 c1 = *(const float4*)&Bs[b][k][tx * 8 + 4];
            float av8[8] = {a0.x, a0.y, a0.z, a0.w, a1.x, a1.y, a1.z, a1.w};
            float bv8[8] = {c0.x, c0.y, c0.z, c0.w, c1.x, c1.y, c1.z, c1.w};
#pragma unroll
            for (int i = 0; i < 8; i++)
#pragma unroll
                for (int j = 0; j < 8; j++) acc[i][j] += av8[i] * bv8[j];
        }
        if (p + 1 < nP) { storeP((p + 1) & 1); __syncthreads(); }
    }
#pragma unroll
    for (int i = 0; i < 8; i++) {
        int row = m0 + ty * 8 + i;
        if (row < M) {
#pragma unroll
            for (int j = 0; j < 8; j++) {
                int col = n0 + tx * 8 + j;
                if (col < N) {
                    float v = acc[i][j] + (bias ? bias[col] : 0.f);
                    if (act) v = tanhf(v);
                    C[(size_t)row * N + col] = v;
                }
            }
        }
    }
}

// ---------------- fused LSTM recurrence step v4 (proven best) --------
// grid (10, 8, 2) = 160 CTAs x 128 threads. CTA = (4 gates x 32 units) x 16 rows.
// Thread = 4 cols (one gate) x 4 rows -> 16 FFMA per k vs 1 LDS.128 + 4 LDS.32.
// Whh streamed in 20-k panels, double-buffered with register prefetch.
__device__ __forceinline__ float sigm(float x) { return 1.f / (1.f + expf(-x)); }

__global__ void __launch_bounds__(128)
lstm_step(const float* __restrict__ WhhF, const float* __restrict__ WhhB,
          int t, int Lcur, int isq) {
    const int tid = threadIdx.x;
    const int tx = tid & 31;   // col-group: cols tx*4..+3 (gate = tx>>3)
    const int ty = tid >> 5;   // 0..3 -> rows ty+4j
    const int ub = blockIdx.x, rbk = blockIdx.y, dir = blockIdx.z;
    const int u0 = ub * 32, n0 = rbk * 16;

    const float* __restrict__ Whh = dir ? WhhB : WhhF;
    const float* __restrict__ G = isq ? (dir ? d_Gqb : d_Gqf)
                                      : (dir ? d_Gb : d_Gf);
    float* hbase = isq ? d_hq : d_h;
    float* cbuf = (isq ? d_cq : d_c) + dir * (NB * HD);
    const float* hp = hbase + (dir * 2 + (t & 1)) * (NB * HD);
    float* hn = hbase + (dir * 2 + ((t + 1) & 1)) * (NB * HD);
    float* Hc = isq ? d_HcatQ : d_Hcat;
    const int tpos = dir ? (Lcur - 1 - t) : t;

    __shared__ __align__(16) float h_s[16][304];     // h_prev rows
    __shared__ __align__(16) float Ws[2][20][128];   // double-buffered k-panels
    __shared__ __align__(16) float gs[16][128];      // staged gates

    // --- issue acc-init gate loads first (independent global traffic) ---
    const int gate = tx >> 3;
    const int un = u0 + (tx & 7) * 4;
    const bool uval = (un < HD);
    float acc[4][4];
#pragma unroll
    for (int j = 0; j < 4; j++) {
        if (uval) {
            int n = n0 + ty + 4 * j;
            float4 v = *(const float4*)(G + ((size_t)n * Lcur + tpos) * GW
                                          + gate * HD + un);
            acc[j][0] = v.x; acc[j][1] = v.y; acc[j][2] = v.z; acc[j][3] = v.w;
        } else {
            acc[j][0] = acc[j][1] = acc[j][2] = acc[j][3] = 0.f;
        }
    }

    // --- h_prev staging: LDG phase (full MLP) then STS phase ---
    float4 hreg[10];
#pragma unroll
    for (int q = 0; q < 10; q++) {
        int i = tid + q * 128;
        if (i < 1200) {
            int r = i / 75, c = i - r * 75;
            hreg[q] = *((const float4*)(hp + (size_t)(n0 + r) * HD) + c);
        }
    }
#pragma unroll
    for (int q = 0; q < 10; q++) {
        int i = tid + q * 128;
        if (i < 1200) {
            int r = i / 75, c = i - r * 75;
            *((float4*)&h_s[r][0] + c) = hreg[q];
        }
    }

    // --- Whh panel pipeline (20 k per panel, 15 panels) ---
    const int lrow = (tid >> 5) * HD + u0 + (tid & 31);
    const bool lval = (u0 + (tid & 31)) < HD;
    float4 pre[5];

    // prologue: panel 0
    if (lval) {
        const float* src = Whh + (size_t)lrow * HD;
#pragma unroll
        for (int q = 0; q < 5; q++) pre[q] = ((const float4*)src)[q];
    }
    if (lval) {
#pragma unroll
        for (int q = 0; q < 5; q++) {
            Ws[0][q * 4 + 0][tid] = pre[q].x;
            Ws[0][q * 4 + 1][tid] = pre[q].y;
            Ws[0][q * 4 + 2][tid] = pre[q].z;
            Ws[0][q * 4 + 3][tid] = pre[q].w;
        }
    } else {
#pragma unroll
        for (int kk = 0; kk < 20; kk++) Ws[0][kk][tid] = 0.f;
    }
    __syncthreads();  // panel 0 + h_s visible

    for (int p = 0; p < 15; p++) {
        if (p + 1 < 15) {
            if (lval) {
                const float* src = Whh + (size_t)lrow * HD + (p + 1) * 20;
#pragma unroll
                for (int q = 0; q < 5; q++) pre[q] = ((const float4*)src)[q];
            }
        }
        const int b = p & 1, k0 = p * 20;
#pragma unroll
        for (int kk = 0; kk < 20; kk++) {
            float4 w = *(const float4*)&Ws[b][kk][tx * 4];
            float h0 = h_s[ty][k0 + kk];
            float h1 = h_s[ty + 4][k0 + kk];
            float h2 = h_s[ty + 8][k0 + kk];
            float h3 = h_s[ty + 12][k0 + kk];
            acc[0][0] += h0 * w.x; acc[0][1] += h0 * w.y;
            acc[0][2] += h0 * w.z; acc[0][3] += h0 * w.w;
            acc[1][0] += h1 * w.x; acc[1][1] += h1 * w.y;
            acc[1][2] += h1 * w.z; acc[1][3] += h1 * w.w;
            acc[2][0] += h2 * w.x; acc[2][1] += h2 * w.y;
            acc[2][2] += h2 * w.z; acc[2][3] += h2 * w.w;
            acc[3][0] += h3 * w.x; acc[3][1] += h3 * w.y;
            acc[3][2] += h3 * w.z; acc[3][3] += h3 * w.w;
        }
        if (p + 1 < 15) {
            const int nb = (p + 1) & 1;
            if (lval) {
#pragma unroll
                for (int q = 0; q < 5; q++) {
                    Ws[nb][q * 4 + 0][tid] = pre[q].x;
                    Ws[nb][q * 4 + 1][tid] = pre[q].y;
                    Ws[nb][q * 4 + 2][tid] = pre[q].z;
                    Ws[nb][q * 4 + 3][tid] = pre[q].w;
                }
            } else {
#pragma unroll
                for (int kk = 0; kk < 20; kk++) Ws[nb][kk][tid] = 0.f;
            }
            __syncthreads();
        }
    }

    // regroup gates through smem (thread holds 4 cols of ONE gate x 4 rows)
#pragma unroll
    for (int j = 0; j < 4; j++) {
        int r = ty + 4 * j;
        *(float4*)&gs[r][tx * 4] = make_float4(acc[j][0], acc[j][1],
                                               acc[j][2], acc[j][3]);
    }
    __syncthreads();

    // cell update: 4 (unit,row) pairs per thread
    for (int p = tid; p < 512; p += 128) {
        int ulane = p & 31, r = p >> 5;
        int u = u0 + ulane;
        if (u < HD) {
            int n = n0 + r;
            float gi = gs[r][ulane];
            float gf = gs[r][32 + ulane];
            float gg = gs[r][64 + ulane];
            float go = gs[r][96 + ulane];
            float cold = cbuf[n * HD + u];
            float cn = sigm(gf) * cold + sigm(gi) * tanhf(gg);
            float hv = sigm(go) * tanhf(cn);
            cbuf[n * HD + u] = cn;
            hn[n * HD + u] = hv;
            Hc[((size_t)n * Lcur + tpos) * (2 * HD) + dir * HD + u] = hv;
        }
    }
}

// ---------------- attention dot: s[m] = dot(X[m,:], av) ----------------
__global__ void att_dot(const float* __restrict__ X, const float* __restrict__ av,
                        float* __restrict__ out, int M) {
    int w = (blockIdx.x * blockDim.x + threadIdx.x) >> 5;
    int lane = threadIdx.x & 31;
    if (w >= M) return;
    const float* x = X + (size_t)w * HD;
    float a = 0.f;
    for (int d = lane; d < HD; d += 32) a += x[d] * av[d];
#pragma unroll
    for (int o = 16; o; o >>= 1) a += __shfl_down_sync(0xffffffffu, a, o);
    if (lane == 0) out[w] = a;
}

// ---------------- query softmax pool ----------------
__global__ void qpool_k() {
    int n = blockIdx.x, tid = threadIdx.x;  // 128 threads
    __shared__ float sc[QL];
    if (tid < QL) sc[tid] = d_sq[n * QL + tid];
    __syncthreads();
    float mx = -1e30f;
#pragma unroll
    for (int l = 0; l < QL; l++) mx = fmaxf(mx, sc[l]);
    float e[QL], sum = 0.f;
#pragma unroll
    for (int l = 0; l < QL; l++) { e[l] = expf(sc[l] - mx); sum += e[l]; }
    float inv = 1.f / sum;
    for (int d = tid; d < HD; d += 128) {
        float a = 0.f;
#pragma unroll
        for (int l = 0; l < QL; l++) a += e[l] * d_qenc[(n * QL + l) * HD + d];
        d_qv[n * HD + d] = a * inv;
    }
}

// ---------------- normalize query: qn = qp / max(||qp||, eps) ----------------
__global__ void qnorm_k() {
    int n = blockIdx.x, tid = threadIdx.x;  // 128 threads
    __shared__ float red[128];
    float ss = 0.f;
    for (int d = tid; d < HD; d += 128) { float v = d_qp[n * HD + d]; ss += v * v; }
    red[tid] = ss;
    __syncthreads();
    for (int s = 64; s; s >>= 1) { if (tid < s) red[tid] += red[tid + s]; __syncthreads(); }
    float inv = 1.f / fmaxf(sqrtf(red[0]), EPSN);
    for (int d = tid; d < HD; d += 128) d_qn[n * HD + d] = d_qp[n * HD + d] * inv;
}

// ---------------- final: sliding-window combos + cosines + mix ----------------
__global__ void final_k(const float* __restrict__ sw, const float* __restrict__ P,
                        float* __restrict__ out) {
    int w = (blockIdx.x * blockDim.x + threadIdx.x) >> 5;
    int lane = threadIdx.x & 31;
    if (w >= MS) return;
    int n = w >> 8, l = w & 255;
    int ln = (l + 1 < SL) ? l + 1 : SL - 1;
    int lp = (l > 0) ? l - 1 : 0;
    float sl = d_s[n * SL + l];
    float sn = d_s[n * SL + ln];
    float sp = d_s[n * SL + lp];
    float m1 = fmaxf(sl, sn);
    float e0 = expf(sl - m1), e1 = expf(sn - m1);
    float wf0 = e0 / (e0 + e1), wf1 = 1.f - wf0;
    float m2 = fmaxf(sp, sl);
    float f0 = expf(sp - m2), f1 = expf(sl - m2);
    float wb0 = f0 / (f0 + f1), wb1 = 1.f - wb0;

    const float* Pl = P + (size_t)(n * SL + l) * HD;
    const float* Pn = P + (size_t)(n * SL + ln) * HD;
    const float* Pp = P + (size_t)(n * SL + lp) * HD;
    const float* q = d_qn + n * HD;

    float dpq = 0.f, dpp = 0.f, duq = 0.f, duu = 0.f, dvq = 0.f, dvv = 0.f;
    for (int d = lane; d < HD; d += 32) {
        float p = Pl[d], pn = Pn[d], pp = Pp[d], qd = q[d];
        float u = wf0 * p + wf1 * pn;
        float v = wb0 * pp + wb1 * p;
        dpq += p * qd; dpp += p * p;
        duq += u * qd; duu += u * u;
        dvq += v * qd; dvv += v * v;
    }
#pragma unroll
    for (int o = 16; o; o >>= 1) {
        dpq += __shfl_down_sync(0xffffffffu, dpq, o);
        dpp += __shfl_down_sync(0xffffffffu, dpp, o);
        duq += __shfl_down_sync(0xffffffffu, duq, o);
        duu += __shfl_down_sync(0xffffffffu, duu, o);
        dvq += __shfl_down_sync(0xffffffffu, dvq, o);
        dvv += __shfl_down_sync(0xffffffffu, dvv, o);
    }
    if (lane == 0) {
        float c1 = dpq / fmaxf(sqrtf(dpp), EPSN);
        float c2 = duq / fmaxf(sqrtf(duu), EPSN);
        float c3 = dvq / fmaxf(sqrtf(dvv), EPSN);
        out[w] = c1 * sw[0] + c2 * sw[1] + c3 * sw[2];
    }
}

// ---------------- launch ----------------
extern "C" void kernel_launch(void* const* d_in, const int* in_sizes, int n_in,
                              void* d_out, int out_size) {
    const int*   seqs = (const int*)d_in[0];
    const int*   quer = (const int*)d_in[1];
    const float* emb  = (const float*)d_in[2];
    const float* WihF = (const float*)d_in[3];
    const float* WhhF = (const float*)d_in[4];
    const float* bihF = (const float*)d_in[5];
    const float* bhhF = (const float*)d_in[6];
    const float* WihB = (const float*)d_in[7];
    const float* WhhB = (const float*)d_in[8];
    const float* bihB = (const float*)d_in[9];
    const float* bhhB = (const float*)d_in[10];
    const float* Wc   = (const float*)d_in[11];
    const float* bc   = (const float*)d_in[12];
    const float* Wa   = (const float*)d_in[13];
    const float* ba   = (const float*)d_in[14];
    const float* av   = (const float*)d_in[15];
    const float* Wf   = (const float*)d_in[16];
    const float* sw   = (const float*)d_in[17];

    void* p;
    cudaGetSymbolAddress(&p, d_Gf);    float* pGf    = (float*)p;
    cudaGetSymbolAddress(&p, d_Gb);    float* pGb    = (float*)p;
    cudaGetSymbolAddress(&p, d_Gqf);   float* pGqf   = (float*)p;
    cudaGetSymbolAddress(&p, d_Gqb);   float* pGqb   = (float*)p;
    cudaGetSymbolAddress(&p, d_Hcat);  float* pHcat  = (float*)p;
    cudaGetSymbolAddress(&p, d_HcatQ); float* pHcatQ = (float*)p;
    cudaGetSymbolAddress(&p, d_hs);    float* phs    = (float*)p;
    cudaGetSymbolAddress(&p, d_qenc);  float* pqenc  = (float*)p;
    cudaGetSymbolAddress(&p, d_tmp);   float* ptmp   = (float*)p;  // doubles as P
    cudaGetSymbolAddress(&p, d_tmpq);  float* ptmpq  = (float*)p;
    cudaGetSymbolAddress(&p, d_s);     float* ps     = (float*)p;
    cudaGetSymbolAddress(&p, d_sq);    float* psq    = (float*)p;
    cudaGetSymbolAddress(&p, d_qv);    float* pqv    = (float*)p;
    cudaGetSymbolAddress(&p, d_qp);    float* pqp    = (float*)p;

    init_state<<<600, 256>>>();

    // input projections (gather + GEMM + both biases)
    dim3 gp(10, 256);
    proj_gemm<<<gp, 256>>>(seqs, emb, WihF, bihF, bhhF, pGf, MS);
    proj_gemm<<<gp, 256>>>(seqs, emb, WihB, bihB, bhhB, pGb, MS);
    dim3 gpq(10, 8);
    proj_gemm<<<gpq, 256>>>(quer, emb, WihF, bihF, bhhF, pGqf, MQ);
    proj_gemm<<<gpq, 256>>>(quer, emb, WihB, bihB, bhhB, pGqb, MQ);

    // recurrences: one launch per timestep, both dirs (proven-safe structure)
    dim3 gl(10, 8, 2);
    for (int t = 0; t < SL; t++) lstm_step<<<gl, 128>>>(WhhF, WhhB, t, SL, 0);
    for (int t = 0; t < QL; t++) lstm_step<<<gl, 128>>>(WhhF, WhhB, t, QL, 1);

    // combine directions: hs = Hcat @ Wc^T + bc
    gemm_k<<<dim3(3, 256), 256>>>(pHcat, Wc, bc, phs, MS, HD, 2 * HD, 1, 0);
    gemm_k<<<dim3(3, 8), 256>>>(pHcatQ, Wc, bc, pqenc, MQ, HD, 2 * HD, 1, 0);

    // attention logits: tanh(X @ Wa^T + ba) . att_vec
    gemm_k<<<dim3(3, 256), 256>>>(phs, Wa, ba, ptmp, MS, HD, HD, 1, 1);
    gemm_k<<<dim3(3, 8), 256>>>(pqenc, Wa, ba, ptmpq, MQ, HD, HD, 1, 1);
    att_dot<<<MS / 8, 256>>>(ptmp, av, ps, MS);
    att_dot<<<MQ / 8, 256>>>(ptmpq, av, psq, MQ);

    // pooled, projected, normalized query
    qpool_k<<<NB, 128>>>();
    gemm_k<<<dim3(3, 1), 256>>>(pqv, Wf, nullptr, pqp, NB, HD, HD, 0, 0);
    qnorm_k<<<NB, 128>>>();

    // P = hs @ Wf  (fwd/bwd combos are linear in hs, so one projection suffices)
    gemm_k<<<dim3(3, 256), 256>>>(phs, Wf, nullptr, ptmp, MS, HD, HD, 0, 0);

    final_k<<<MS / 8, 256>>>(sw, ptmp, (float*)d_out);
}

// round 12
// speedup vs baseline: 1.2489x; 1.0670x over previous
#include <cuda_runtime.h>
#include <math.h>

static constexpr int NB = 128;     // batch
static constexpr int SL = 256;     // seq len
static constexpr int QL = 8;       // query len
static constexpr int ED = 300;     // embed dim
static constexpr int HD = 300;     // hidden dim
static constexpr int GW = 1200;    // 4*HD gate width
static constexpr int MS = NB * SL; // 32768
static constexpr int MQ = NB * QL; // 1024
static constexpr float EPSN = 1e-12f;

// lstm partition: 10 unit-blocks x 7 row-blocks x 2 dirs = 140 CTAs (<=148 SMs,
// single wave -- the previous 160-CTA grid double-loaded 12 SMs and doubled
// effective step latency)
static constexpr int RBL = 7;
static constexpr int ROWS = 19;    // 7*19 = 133 >= 128 (tail guarded)

// ---------------- static device scratch (no runtime allocation) ----------------
__device__ float d_Gf[MS * GW];        // input-proj gates, seqs forward  (incl. biases)
__device__ float d_Gb[MS * GW];        // seqs backward
__device__ float d_Gqf[MQ * GW];       // queries forward
__device__ float d_Gqb[MQ * GW];       // queries backward
__device__ float d_Hcat[MS * 2 * HD];  // [N, L, 2H] concat(hf, hb)
__device__ float d_HcatQ[MQ * 2 * HD];
__device__ float d_h[2 * 2 * NB * HD]; // [dir][parity][N*H] ping-pong hidden
__device__ float d_c[2 * NB * HD];     // [dir][N*H] cell (seqs)
__device__ float d_hq[2 * 2 * NB * HD];
__device__ float d_cq[2 * NB * HD];    // cell (queries)
__device__ float d_hs[MS * HD];        // encoded seq states
__device__ float d_qenc[MQ * HD];      // encoded query states
__device__ float d_tmp[MS * HD];       // tanh(hs@Wa^T+ba); later reused as P = hs@Wf
__device__ float d_tmpq[MQ * HD];
__device__ float d_s[MS];              // attention logits (seqs)
__device__ float d_sq[MQ];             // attention logits (queries)
__device__ float d_qv[NB * HD];        // pooled query vec
__device__ float d_qp[NB * HD];        // qv @ Wf
__device__ float d_qn[NB * HD];        // normalized

// ---------------- init ----------------
__global__ void init_state() {
    int i = blockIdx.x * blockDim.x + threadIdx.x;
    if (i < 2 * 2 * NB * HD) { d_h[i] = 0.f; d_hq[i] = 0.f; }
    if (i < 2 * NB * HD)     { d_c[i] = 0.f; d_cq[i] = 0.f; }
}

// ---------------- gathered input-projection GEMM (double-buffered) ----------------
// G[m, j] = sum_e emb[tok[m], e] * W[j, e] + b1[j] + b2[j]    (M x 1200, K=300)
__global__ void __launch_bounds__(256, 2)
proj_gemm(const int* __restrict__ tok, const float* __restrict__ emb,
          const float* __restrict__ W, const float* __restrict__ b1,
          const float* __restrict__ b2, float* __restrict__ G, int M) {
    __shared__ __align__(16) float As[2][8][128];
    __shared__ __align__(16) float Bs[2][8][128];
    int tid = threadIdx.x;
    int m0 = blockIdx.y * 128, n0 = blockIdx.x * 128;
    int tx = tid % 16, ty = tid / 16;
    int am = tid >> 1, akq = (tid & 1) * 4;
    int arow = m0 + am;
    const float* aptr = emb + (size_t)((arow < M) ? tok[arow] : 0) * ED;
    int bcol = n0 + am;
    float acc[8][8];
#pragma unroll
    for (int i = 0; i < 8; i++)
#pragma unroll
        for (int j = 0; j < 8; j++) acc[i][j] = 0.f;

    float ra[4], rbv[4];
    const int nP = (ED + 7) / 8;  // 38

#pragma unroll
    for (int j = 0; j < 4; j++) {
        int kk = akq + j;
        ra[j]  = (arow < M && kk < ED) ? aptr[kk] : 0.f;
        rbv[j] = (bcol < GW && kk < ED) ? W[(size_t)bcol * ED + kk] : 0.f;
    }
#pragma unroll
    for (int j = 0; j < 4; j++) { As[0][akq + j][am] = ra[j]; Bs[0][akq + j][am] = rbv[j]; }
    __syncthreads();

    for (int p = 0; p < nP; p++) {
        if (p + 1 < nP) {
            int k0 = (p + 1) * 8;
#pragma unroll
            for (int j = 0; j < 4; j++) {
                int kk = k0 + akq + j;
                ra[j]  = (arow < M && kk < ED) ? aptr[kk] : 0.f;
                rbv[j] = (bcol < GW && kk < ED) ? W[(size_t)bcol * ED + kk] : 0.f;
            }
        }
        int b = p & 1;
#pragma unroll
        for (int k = 0; k < 8; k++) {
            float4 a0 = *(const float4*)&As[b][k][ty * 8];
            float4 a1 = *(const float4*)&As[b][k][ty * 8 + 4];
            float4 c0 = *(const float4*)&Bs[b][k][tx * 8];
            float4 c1 = *(const float4*)&Bs[b][k][tx * 8 + 4];
            float av8[8] = {a0.x, a0.y, a0.z, a0.w, a1.x, a1.y, a1.z, a1.w};
            float bv8[8] = {c0.x, c0.y, c0.z, c0.w, c1.x, c1.y, c1.z, c1.w};
#pragma unroll
            for (int i = 0; i < 8; i++)
#pragma unroll
                for (int j = 0; j < 8; j++) acc[i][j] += av8[i] * bv8[j];
        }
        if (p + 1 < nP) {
            int nb = (p + 1) & 1;
#pragma unroll
            for (int j = 0; j < 4; j++) { As[nb][akq + j][am] = ra[j]; Bs[nb][akq + j][am] = rbv[j]; }
            __syncthreads();
        }
    }
#pragma unroll
    for (int i = 0; i < 8; i++) {
        int row = m0 + ty * 8 + i;
        if (row < M) {
#pragma unroll
            for (int j = 0; j < 8; j++) {
                int col = n0 + tx * 8 + j;
                if (col < GW) G[(size_t)row * GW + col] = acc[i][j] + b1[col] + b2[col];
            }
        }
    }
}

// ---------------- generic SGEMM (double-buffered) ----------------
__global__ void __launch_bounds__(256, 2)
gemm_k(const float* __restrict__ A, const float* __restrict__ B,
       const float* __restrict__ bias, float* __restrict__ C,
       int M, int N, int K, int transB, int act) {
    __shared__ __align__(16) float As[2][8][128];
    __shared__ __align__(16) float Bs[2][8][128];
    int tid = threadIdx.x;
    int m0 = blockIdx.y * 128, n0 = blockIdx.x * 128;
    int tx = tid % 16, ty = tid / 16;
    int am = tid >> 1, akq = (tid & 1) * 4;
    int arow = m0 + am, bcol = n0 + am;
    float acc[8][8];
#pragma unroll
    for (int i = 0; i < 8; i++)
#pragma unroll
        for (int j = 0; j < 8; j++) acc[i][j] = 0.f;

    float ra[4], rbv[4];
    const int nP = (K + 7) / 8;

    auto loadP = [&](int k0) {
#pragma unroll
        for (int j = 0; j < 4; j++) {
            int kk = k0 + akq + j;
            ra[j] = (arow < M && kk < K) ? A[(size_t)arow * K + kk] : 0.f;
        }
        if (transB) {
#pragma unroll
            for (int j = 0; j < 4; j++) {
                int kk = k0 + akq + j;
                rbv[j] = (bcol < N && kk < K) ? B[(size_t)bcol * K + kk] : 0.f;
            }
        } else {
#pragma unroll
            for (int i = 0; i < 4; i++) {
                int idx = tid + i * 256;
                int k = idx >> 7, j = idx & 127;
                rbv[i] = (k0 + k < K && n0 + j < N) ? B[(size_t)(k0 + k) * N + n0 + j] : 0.f;
            }
        }
    };
    auto storeP = [&](int b) {
#pragma unroll
        for (int j = 0; j < 4; j++) As[b][akq + j][am] = ra[j];
        if (transB) {
#pragma unroll
            for (int j = 0; j < 4; j++) Bs[b][akq + j][am] = rbv[j];
        } else {
#pragma unroll
            for (int i = 0; i < 4; i++) {
                int idx = tid + i * 256;
                Bs[b][idx >> 7][idx & 127] = rbv[i];
            }
        }
    };

    loadP(0); storeP(0);
    __syncthreads();

    for (int p = 0; p < nP; p++) {
        if (p + 1 < nP) loadP((p + 1) * 8);
        int b = p & 1;
#pragma unroll
        for (int k = 0; k < 8; k++) {
            float4 a0 = *(const float4*)&As[b][k][ty * 8];
            float4 a1 = *(const float4*)&As[b][k][ty * 8 + 4];
            float4 c0 = *(const float4*)&Bs[b][k][tx * 8];
            float4 c1 = *(const float4*)&Bs[b][k][tx * 8 + 4];
            float av8[8] = {a0.x, a0.y, a0.z, a0.w, a1.x, a1.y, a1.z, a1.w};
            float bv8[8] = {c0.x, c0.y, c0.z, c0.w, c1.x, c1.y, c1.z, c1.w};
#pragma unroll
            for (int i = 0; i < 8; i++)
#pragma unroll
                for (int j = 0; j < 8; j++) acc[i][j] += av8[i] * bv8[j];
        }
        if (p + 1 < nP) { storeP((p + 1) & 1); __syncthreads(); }
    }
#pragma unroll
    for (int i = 0; i < 8; i++) {
        int row = m0 + ty * 8 + i;
        if (row < M) {
#pragma unroll
            for (int j = 0; j < 8; j++) {
                int col = n0 + tx * 8 + j;
                if (col < N) {
                    float v = acc[i][j] + (bias ? bias[col] : 0.f);
                    if (act) v = tanhf(v);
                    C[(size_t)row * N + col] = v;
                }
            }
        }
    }
}

// ---------------- fused LSTM recurrence step v6 (single-wave grid) --------------
// grid (10, 7, 2) = 140 CTAs x 128 threads (one wave on 148 SMs; the previous
// 160-CTA grid double-loaded 12 SMs). CTA = (4 gates x 32 units) x 19 rows.
// Thread = 4 cols (one gate) x 5 rows -> 20 FFMA per k vs 1 LDS.128 + 5 LDS.32.
// Whh streamed in 20-k panels, double-buffered. gs aliases the dead Ws[1]
// buffer (last panel p=14 reads only Ws[0]; Ws[1] dead after p=13 barrier).
__device__ __forceinline__ float sigm(float x) { return 1.f / (1.f + expf(-x)); }

__global__ void __launch_bounds__(128)
lstm_step(const float* __restrict__ WhhF, const float* __restrict__ WhhB,
          int t, int Lcur, int isq) {
    const int tid = threadIdx.x;
    const int tx = tid & 31;   // col-group: cols tx*4..+3 (gate = tx>>3)
    const int ty = tid >> 5;   // 0..3 -> rows ty+4j, j<5
    const int ub = blockIdx.x, rbk = blockIdx.y, dir = blockIdx.z;
    const int u0 = ub * 32, n0 = rbk * ROWS;

    const float* __restrict__ Whh = dir ? WhhB : WhhF;
    const float* __restrict__ G = isq ? (dir ? d_Gqb : d_Gqf)
                                      : (dir ? d_Gb : d_Gf);
    float* hbase = isq ? d_hq : d_h;
    float* cbuf = (isq ? d_cq : d_c) + dir * (NB * HD);
    const float* hp = hbase + (dir * 2 + (t & 1)) * (NB * HD);
    float* hn = hbase + (dir * 2 + ((t + 1) & 1)) * (NB * HD);
    float* Hc = isq ? d_HcatQ : d_Hcat;
    const int tpos = dir ? (Lcur - 1 - t) : t;

    __shared__ __align__(16) float h_s[ROWS][300];   // h_prev rows (22800 B)
    __shared__ __align__(16) float Ws[2][20][128];   // double-buffered k-panels
    float* gs = &Ws[1][0][0];                        // aliased gate stage (2432 fl)

    // --- acc init: this step's input-proj gates (biases included) ---
    const int gate = tx >> 3;
    const int un = u0 + (tx & 7) * 4;
    const bool uval = (un < HD);
    float acc[5][4];
#pragma unroll
    for (int j = 0; j < 5; j++) {
        int r = ty + 4 * j, n = n0 + r;
        if (uval && r < ROWS && n < NB) {
            float4 v = *(const float4*)(G + ((size_t)n * Lcur + tpos) * GW
                                          + gate * HD + un);
            acc[j][0] = v.x; acc[j][1] = v.y; acc[j][2] = v.z; acc[j][3] = v.w;
        } else {
            acc[j][0] = acc[j][1] = acc[j][2] = acc[j][3] = 0.f;
        }
    }

    // --- h_prev staging: LDG phase (full MLP) then STS phase; OOB rows clamped ---
    float4 hreg[12];
#pragma unroll
    for (int q = 0; q < 12; q++) {
        int i = tid + q * 128;
        if (i < ROWS * 75) {
            int r = i / 75, c = i - r * 75;
            int n = n0 + r; if (n >= NB) n = NB - 1;
            hreg[q] = *((const float4*)(hp + (size_t)n * HD) + c);
        }
    }
#pragma unroll
    for (int q = 0; q < 12; q++) {
        int i = tid + q * 128;
        if (i < ROWS * 75) {
            int r = i / 75, c = i - r * 75;
            *((float4*)&h_s[r][0] + c) = hreg[q];
        }
    }

    // --- Whh panel pipeline (20 k per panel, 15 panels, double-buffered) ---
    const int lrow = (tid >> 5) * HD + u0 + (tid & 31);
    const bool lval = (u0 + (tid & 31)) < HD;
    float4 pre[5];

    // prologue: panel 0
    if (lval) {
        const float* src = Whh + (size_t)lrow * HD;
#pragma unroll
        for (int q = 0; q < 5; q++) pre[q] = ((const float4*)src)[q];
#pragma unroll
        for (int q = 0; q < 5; q++) {
            Ws[0][q * 4 + 0][tid] = pre[q].x;
            Ws[0][q * 4 + 1][tid] = pre[q].y;
            Ws[0][q * 4 + 2][tid] = pre[q].z;
            Ws[0][q * 4 + 3][tid] = pre[q].w;
        }
    } else {
#pragma unroll
        for (int kk = 0; kk < 20; kk++) Ws[0][kk][tid] = 0.f;
    }
    __syncthreads();  // panel 0 + h_s visible

    for (int p = 0; p < 15; p++) {
        if (p + 1 < 15 && lval) {
            const float* src = Whh + (size_t)lrow * HD + (p + 1) * 20;
#pragma unroll
            for (int q = 0; q < 5; q++) pre[q] = ((const float4*)src)[q];
        }
        const int b = p & 1, k0 = p * 20;
#pragma unroll
        for (int kk = 0; kk < 20; kk++) {
            float4 w = *(const float4*)&Ws[b][kk][tx * 4];
            float h0 = h_s[ty][k0 + kk];
            float h1 = h_s[ty + 4][k0 + kk];
            float h2 = h_s[ty + 8][k0 + kk];
            float h3 = h_s[ty + 12][k0 + kk];
            float h4 = (ty < 3) ? h_s[ty + 16][k0 + kk] : 0.f;
            acc[0][0] += h0 * w.x; acc[0][1] += h0 * w.y;
            acc[0][2] += h0 * w.z; acc[0][3] += h0 * w.w;
            acc[1][0] += h1 * w.x; acc[1][1] += h1 * w.y;
            acc[1][2] += h1 * w.z; acc[1][3] += h1 * w.w;
            acc[2][0] += h2 * w.x; acc[2][1] += h2 * w.y;
            acc[2][2] += h2 * w.z; acc[2][3] += h2 * w.w;
            acc[3][0] += h3 * w.x; acc[3][1] += h3 * w.y;
            acc[3][2] += h3 * w.z; acc[3][3] += h3 * w.w;
            acc[4][0] += h4 * w.x; acc[4][1] += h4 * w.y;
            acc[4][2] += h4 * w.z; acc[4][3] += h4 * w.w;
        }
        if (p + 1 < 15) {
            const int nb = (p + 1) & 1;
            if (lval) {
#pragma unroll
                for (int q = 0; q < 5; q++) {
                    Ws[nb][q * 4 + 0][tid] = pre[q].x;
                    Ws[nb][q * 4 + 1][tid] = pre[q].y;
                    Ws[nb][q * 4 + 2][tid] = pre[q].z;
                    Ws[nb][q * 4 + 3][tid] = pre[q].w;
                }
            } else {
#pragma unroll
                for (int kk = 0; kk < 20; kk++) Ws[nb][kk][tid] = 0.f;
            }
            __syncthreads();
        }
    }

    // regroup gates into aliased gs (Ws[1] is dead: panel 14 read only Ws[0])
#pragma unroll
    for (int j = 0; j < 5; j++) {
        int r = ty + 4 * j;
        if (r < ROWS)
            *(float4*)&gs[r * 128 + tx * 4] = make_float4(acc[j][0], acc[j][1],
                                                          acc[j][2], acc[j][3]);
    }
    __syncthreads();

    // cell update: up to 5 (unit,row) pairs per thread
    for (int p = tid; p < ROWS * 32; p += 128) {
        int ulane = p & 31, r = p >> 5;
        int u = u0 + ulane, n = n0 + r;
        if (u < HD && n < NB) {
            float gi = gs[r * 128 + ulane];
            float gf = gs[r * 128 + 32 + ulane];
            float gg = gs[r * 128 + 64 + ulane];
            float go = gs[r * 128 + 96 + ulane];
            float cold = cbuf[n * HD + u];
            float cn = sigm(gf) * cold + sigm(gi) * tanhf(gg);
            float hv = sigm(go) * tanhf(cn);
            cbuf[n * HD + u] = cn;
            hn[n * HD + u] = hv;
            Hc[((size_t)n * Lcur + tpos) * (2 * HD) + dir * HD + u] = hv;
        }
    }
}

// ---------------- attention dot: s[m] = dot(X[m,:], av) ----------------
__global__ void att_dot(const float* __restrict__ X, const float* __restrict__ av,
                        float* __restrict__ out, int M) {
    int w = (blockIdx.x * blockDim.x + threadIdx.x) >> 5;
    int lane = threadIdx.x & 31;
    if (w >= M) return;
    const float* x = X + (size_t)w * HD;
    float a = 0.f;
    for (int d = lane; d < HD; d += 32) a += x[d] * av[d];
#pragma unroll
    for (int o = 16; o; o >>= 1) a += __shfl_down_sync(0xffffffffu, a, o);
    if (lane == 0) out[w] = a;
}

// ---------------- query softmax pool ----------------
__global__ void qpool_k() {
    int n = blockIdx.x, tid = threadIdx.x;  // 128 threads
    __shared__ float sc[QL];
    if (tid < QL) sc[tid] = d_sq[n * QL + tid];
    __syncthreads();
    float mx = -1e30f;
#pragma unroll
    for (int l = 0; l < QL; l++) mx = fmaxf(mx, sc[l]);
    float e[QL], sum = 0.f;
#pragma unroll
    for (int l = 0; l < QL; l++) { e[l] = expf(sc[l] - mx); sum += e[l]; }
    float inv = 1.f / sum;
    for (int d = tid; d < HD; d += 128) {
        float a = 0.f;
#pragma unroll
        for (int l = 0; l < QL; l++) a += e[l] * d_qenc[(n * QL + l) * HD + d];
        d_qv[n * HD + d] = a * inv;
    }
}

// ---------------- normalize query: qn = qp / max(||qp||, eps) ----------------
__global__ void qnorm_k() {
    int n = blockIdx.x, tid = threadIdx.x;  // 128 threads
    __shared__ float red[128];
    float ss = 0.f;
    for (int d = tid; d < HD; d += 128) { float v = d_qp[n * HD + d]; ss += v * v; }
    red[tid] = ss;
    __syncthreads();
    for (int s = 64; s; s >>= 1) { if (tid < s) red[tid] += red[tid + s]; __syncthreads(); }
    float inv = 1.f / fmaxf(sqrtf(red[0]), EPSN);
    for (int d = tid; d < HD; d += 128) d_qn[n * HD + d] = d_qp[n * HD + d] * inv;
}

// ---------------- final: sliding-window combos + cosines + mix ----------------
__global__ void final_k(const float* __restrict__ sw, const float* __restrict__ P,
                        float* __restrict__ out) {
    int w = (blockIdx.x * blockDim.x + threadIdx.x) >> 5;
    int lane = threadIdx.x & 31;
    if (w >= MS) return;
    int n = w >> 8, l = w & 255;
    int ln = (l + 1 < SL) ? l + 1 : SL - 1;
    int lp = (l > 0) ? l - 1 : 0;
    float sl = d_s[n * SL + l];
    float sn = d_s[n * SL + ln];
    float sp = d_s[n * SL + lp];
    float m1 = fmaxf(sl, sn);
    float e0 = expf(sl - m1), e1 = expf(sn - m1);
    float wf0 = e0 / (e0 + e1), wf1 = 1.f - wf0;
    float m2 = fmaxf(sp, sl);
    float f0 = expf(sp - m2), f1 = expf(sl - m2);
    float wb0 = f0 / (f0 + f1), wb1 = 1.f - wb0;

    const float* Pl = P + (size_t)(n * SL + l) * HD;
    const float* Pn = P + (size_t)(n * SL + ln) * HD;
    const float* Pp = P + (size_t)(n * SL + lp) * HD;
    const float* q = d_qn + n * HD;

    float dpq = 0.f, dpp = 0.f, duq = 0.f, duu = 0.f, dvq = 0.f, dvv = 0.f;
    for (int d = lane; d < HD; d += 32) {
        float p = Pl[d], pn = Pn[d], pp = Pp[d], qd = q[d];
        float u = wf0 * p + wf1 * pn;
        float v = wb0 * pp + wb1 * p;
        dpq += p * qd; dpp += p * p;
        duq += u * qd; duu += u * u;
        dvq += v * qd; dvv += v * v;
    }
#pragma unroll
    for (int o = 16; o; o >>= 1) {
        dpq += __shfl_down_sync(0xffffffffu, dpq, o);
        dpp += __shfl_down_sync(0xffffffffu, dpp, o);
        duq += __shfl_down_sync(0xffffffffu, duq, o);
        duu += __shfl_down_sync(0xffffffffu, duu, o);
        dvq += __shfl_down_sync(0xffffffffu, dvq, o);
        dvv += __shfl_down_sync(0xffffffffu, dvv, o);
    }
    if (lane == 0) {
        float c1 = dpq / fmaxf(sqrtf(dpp), EPSN);
        float c2 = duq / fmaxf(sqrtf(duu), EPSN);
        float c3 = dvq / fmaxf(sqrtf(dvv), EPSN);
        out[w] = c1 * sw[0] + c2 * sw[1] + c3 * sw[2];
    }
}

// ---------------- launch ----------------
extern "C" void kernel_launch(void* const* d_in, const int* in_sizes, int n_in,
                              void* d_out, int out_size) {
    const int*   seqs = (const int*)d_in[0];
    const int*   quer = (const int*)d_in[1];
    const float* emb  = (const float*)d_in[2];
    const float* WihF = (const float*)d_in[3];
    const float* WhhF = (const float*)d_in[4];
    const float* bihF = (const float*)d_in[5];
    const float* bhhF = (const float*)d_in[6];
    const float* WihB = (const float*)d_in[7];
    const float* WhhB = (const float*)d_in[8];
    const float* bihB = (const float*)d_in[9];
    const float* bhhB = (const float*)d_in[10];
    const float* Wc   = (const float*)d_in[11];
    const float* bc   = (const float*)d_in[12];
    const float* Wa   = (const float*)d_in[13];
    const float* ba   = (const float*)d_in[14];
    const float* av   = (const float*)d_in[15];
    const float* Wf   = (const float*)d_in[16];
    const float* sw   = (const float*)d_in[17];

    void* p;
    cudaGetSymbolAddress(&p, d_Gf);    float* pGf    = (float*)p;
    cudaGetSymbolAddress(&p, d_Gb);    float* pGb    = (float*)p;
    cudaGetSymbolAddress(&p, d_Gqf);   float* pGqf   = (float*)p;
    cudaGetSymbolAddress(&p, d_Gqb);   float* pGqb   = (float*)p;
    cudaGetSymbolAddress(&p, d_Hcat);  float* pHcat  = (float*)p;
    cudaGetSymbolAddress(&p, d_HcatQ); float* pHcatQ = (float*)p;
    cudaGetSymbolAddress(&p, d_hs);    float* phs    = (float*)p;
    cudaGetSymbolAddress(&p, d_qenc);  float* pqenc  = (float*)p;
    cudaGetSymbolAddress(&p, d_tmp);   float* ptmp   = (float*)p;  // doubles as P
    cudaGetSymbolAddress(&p, d_tmpq);  float* ptmpq  = (float*)p;
    cudaGetSymbolAddress(&p, d_s);     float* ps     = (float*)p;
    cudaGetSymbolAddress(&p, d_sq);    float* psq    = (float*)p;
    cudaGetSymbolAddress(&p, d_qv);    float* pqv    = (float*)p;
    cudaGetSymbolAddress(&p, d_qp);    float* pqp    = (float*)p;

    init_state<<<600, 256>>>();

    // input projections (gather + GEMM + both biases)
    dim3 gp(10, 256);
    proj_gemm<<<gp, 256>>>(seqs, emb, WihF, bihF, bhhF, pGf, MS);
    proj_gemm<<<gp, 256>>>(seqs, emb, WihB, bihB, bhhB, pGb, MS);
    dim3 gpq(10, 8);
    proj_gemm<<<gpq, 256>>>(quer, emb, WihF, bihF, bhhF, pGqf, MQ);
    proj_gemm<<<gpq, 256>>>(quer, emb, WihB, bihB, bhhB, pGqb, MQ);

    // recurrences: one launch per timestep, both dirs; 140 CTAs = single wave
    dim3 gl(10, RBL, 2);
    for (int t = 0; t < SL; t++) lstm_step<<<gl, 128>>>(WhhF, WhhB, t, SL, 0);
    for (int t = 0; t < QL; t++) lstm_step<<<gl, 128>>>(WhhF, WhhB, t, QL, 1);

    // combine directions: hs = Hcat @ Wc^T + bc
    gemm_k<<<dim3(3, 256), 256>>>(pHcat, Wc, bc, phs, MS, HD, 2 * HD, 1, 0);
    gemm_k<<<dim3(3, 8), 256>>>(pHcatQ, Wc, bc, pqenc, MQ, HD, 2 * HD, 1, 0);

    // attention logits: tanh(X @ Wa^T + ba) . att_vec
    gemm_k<<<dim3(3, 256), 256>>>(phs, Wa, ba, ptmp, MS, HD, HD, 1, 1);
    gemm_k<<<dim3(3, 8), 256>>>(pqenc, Wa, ba, ptmpq, MQ, HD, HD, 1, 1);
    att_dot<<<MS / 8, 256>>>(ptmp, av, ps, MS);
    att_dot<<<MQ / 8, 256>>>(ptmpq, av, psq, MQ);

    // pooled, projected, normalized query
    qpool_k<<<NB, 128>>>();
    gemm_k<<<dim3(3, 1), 256>>>(pqv, Wf, nullptr, pqp, NB, HD, HD, 0, 0);
    qnorm_k<<<NB, 128>>>();

    // P = hs @ Wf  (fwd/bwd combos are linear in hs, so one projection suffices)
    gemm_k<<<dim3(3, 256), 256>>>(phs, Wf, nullptr, ptmp, MS, HD, HD, 0, 0);

    final_k<<<MS / 8, 256>>>(sw, ptmp, (float*)d_out);
}

// round 14
// speedup vs baseline: 1.5608x; 1.2498x over previous
#include <cuda_runtime.h>
#include <math.h>
#include <stdint.h>

static constexpr int NB = 128;     // batch
static constexpr int SL = 256;     // seq len
static constexpr int QL = 8;       // query len
static constexpr int ED = 300;     // embed dim
static constexpr int HD = 300;     // hidden dim
static constexpr int GW = 1200;    // 4*HD gate width
static constexpr int MS = NB * SL; // 32768
static constexpr int MQ = NB * QL; // 1024
static constexpr float EPSN = 1e-12f;

// lstm partition: 10 x 7 x 2 = 140 CTAs (single wave on 148 SMs)
static constexpr int RBL = 7;
static constexpr int ROWS = 19;    // 7*19 = 133 >= 128 (tail guarded)

static constexpr int SSTR = 136;   // smem k-row stride: (8k+m)%32 conflict-free

// ---------------- static device scratch (no runtime allocation) ----------------
__device__ float d_Gf[MS * GW];
__device__ float d_Gb[MS * GW];
__device__ float d_Gqf[MQ * GW];
__device__ float d_Gqb[MQ * GW];
__device__ float d_Hcat[MS * 2 * HD];
__device__ float d_HcatQ[MQ * 2 * HD];
__device__ float d_h[2 * 2 * NB * HD];
__device__ float d_c[2 * NB * HD];
__device__ float d_hq[2 * 2 * NB * HD];
__device__ float d_cq[2 * NB * HD];
__device__ float d_hs[MS * HD];
__device__ float d_qenc[MQ * HD];
__device__ float d_tmp[MS * HD];
__device__ float d_tmpq[MQ * HD];
__device__ float d_s[MS];
__device__ float d_sq[MQ];
__device__ float d_qv[NB * HD];
__device__ float d_qp[NB * HD];
__device__ float d_qn[NB * HD];

// ---------------- init ----------------
__global__ void init_state() {
    int i = blockIdx.x * blockDim.x + threadIdx.x;
    if (i < 2 * 2 * NB * HD) { d_h[i] = 0.f; d_hq[i] = 0.f; }
    if (i < 2 * NB * HD)     { d_c[i] = 0.f; d_cq[i] = 0.f; }
}

// ---------------- tf32 mma.sync helper ----------------
__device__ __forceinline__ void mma8(float4& c, uint32_t a0, uint32_t a1,
                                     uint32_t a2, uint32_t a3,
                                     uint32_t b0, uint32_t b1) {
    asm volatile(
        "mma.sync.aligned.m16n8k8.row.col.f32.tf32.tf32.f32 "
        "{%0,%1,%2,%3}, {%4,%5,%6,%7}, {%8,%9}, {%0,%1,%2,%3};"
        : "+f"(c.x), "+f"(c.y), "+f"(c.z), "+f"(c.w)
        : "r"(a0), "r"(a1), "r"(a2), "r"(a3), "r"(b0), "r"(b1));
}
__device__ __forceinline__ uint32_t fu(float x) { return __float_as_uint(x); }

// ---------------- tf32 tensor-core GEMM: C = A @ op(B) (+bias)(+tanh) -----------
// CTA 128x128 tile, 8 warps as 4(M) x 2(N); warp tile 32x64 = 2x8 m16n8k8 frags.
// Double-buffered 8-k slabs with register prefetch (proven skeleton).
__global__ void __launch_bounds__(256)
mma_gemm(const float* __restrict__ A, const float* __restrict__ B,
         const float* __restrict__ bias, float* __restrict__ C,
         int M, int N, int K, int transB, int act) {
    __shared__ float As[2][8][SSTR];
    __shared__ float Bs[2][8][SSTR];
    const int tid = threadIdx.x;
    const int m0 = blockIdx.y * 128, n0 = blockIdx.x * 128;
    const int wid = tid >> 5, lane = tid & 31;
    const int wm = wid >> 1, wn = wid & 1;       // warp 32-row / 64-col block
    const int g = lane >> 2, tig = lane & 3;
    const int am = tid >> 1, akq = (tid & 1) * 4;
    const int arow = m0 + am, bcol = n0 + am;

    float4 acc[2][8];
#pragma unroll
    for (int i = 0; i < 2; i++)
#pragma unroll
        for (int j = 0; j < 8; j++) acc[i][j] = make_float4(0.f, 0.f, 0.f, 0.f);

    float ra[4], rb[4];
    const int nP = (K + 7) / 8;

    auto loadP = [&](int k0) {
#pragma unroll
        for (int j = 0; j < 4; j++) {
            int kk = k0 + akq + j;
            ra[j] = (arow < M && kk < K) ? A[(size_t)arow * K + kk] : 0.f;
        }
        if (transB) {
#pragma unroll
            for (int j = 0; j < 4; j++) {
                int kk = k0 + akq + j;
                rb[j] = (bcol < N && kk < K) ? B[(size_t)bcol * K + kk] : 0.f;
            }
        } else {
#pragma unroll
            for (int i = 0; i < 4; i++) {
                int idx = tid + i * 256;
                int k = idx >> 7, n = idx & 127;
                rb[i] = (k0 + k < K && n0 + n < N) ? B[(size_t)(k0 + k) * N + n0 + n] : 0.f;
            }
        }
    };
    auto storeP = [&](int b) {
#pragma unroll
        for (int j = 0; j < 4; j++) As[b][akq + j][am] = ra[j];
        if (transB) {
#pragma unroll
            for (int j = 0; j < 4; j++) Bs[b][akq + j][am] = rb[j];
        } else {
#pragma unroll
            for (int i = 0; i < 4; i++) {
                int idx = tid + i * 256;
                Bs[b][idx >> 7][idx & 127] = rb[i];
            }
        }
    };

    loadP(0); storeP(0);
    __syncthreads();

    for (int p = 0; p < nP; p++) {
        if (p + 1 < nP) loadP((p + 1) * 8);
        const int b = p & 1;
        // A fragments (2 m16 frags for this warp's 32 rows)
        uint32_t af[2][4];
#pragma unroll
        for (int mf = 0; mf < 2; mf++) {
            int r0 = wm * 32 + mf * 16 + g;
            af[mf][0] = fu(As[b][tig][r0]);
            af[mf][1] = fu(As[b][tig][r0 + 8]);
            af[mf][2] = fu(As[b][tig + 4][r0]);
            af[mf][3] = fu(As[b][tig + 4][r0 + 8]);
        }
#pragma unroll
        for (int nf = 0; nf < 8; nf++) {
            int cn = wn * 64 + nf * 8 + g;
            uint32_t b0 = fu(Bs[b][tig][cn]);
            uint32_t b1 = fu(Bs[b][tig + 4][cn]);
            mma8(acc[0][nf], af[0][0], af[0][1], af[0][2], af[0][3], b0, b1);
            mma8(acc[1][nf], af[1][0], af[1][1], af[1][2], af[1][3], b0, b1);
        }
        if (p + 1 < nP) { storeP((p + 1) & 1); __syncthreads(); }
    }

    // epilogue: C fragment map (g,2t),(g,2t+1),(g+8,2t),(g+8,2t+1)
#pragma unroll
    for (int mf = 0; mf < 2; mf++) {
        int r0 = m0 + wm * 32 + mf * 16 + g;
        int r1 = r0 + 8;
#pragma unroll
        for (int nf = 0; nf < 8; nf++) {
            int cc = n0 + wn * 64 + nf * 8 + tig * 2;
            float4 c = acc[mf][nf];
            float bx = (bias && cc < N) ? bias[cc] : 0.f;
            float by = (bias && cc + 1 < N) ? bias[cc + 1] : 0.f;
            float vx0 = c.x + bx, vy0 = c.y + by;
            float vx1 = c.z + bx, vy1 = c.w + by;
            if (act) { vx0 = tanhf(vx0); vy0 = tanhf(vy0);
                       vx1 = tanhf(vx1); vy1 = tanhf(vy1); }
            if (r0 < M) {
                if (cc < N)     C[(size_t)r0 * N + cc]     = vx0;
                if (cc + 1 < N) C[(size_t)r0 * N + cc + 1] = vy0;
            }
            if (r1 < M) {
                if (cc < N)     C[(size_t)r1 * N + cc]     = vx1;
                if (cc + 1 < N) C[(size_t)r1 * N + cc + 1] = vy1;
            }
        }
    }
}

// ---------------- tf32 gathered input-projection GEMM ----------------
// G[m, j] = sum_e emb[tok[m], e] * W[j, e] + b1[j] + b2[j]   (M x 1200, K=300)
__global__ void __launch_bounds__(256)
mma_proj(const int* __restrict__ tok, const float* __restrict__ emb,
         const float* __restrict__ W, const float* __restrict__ b1,
         const float* __restrict__ b2, float* __restrict__ G, int M) {
    __shared__ float As[2][8][SSTR];
    __shared__ float Bs[2][8][SSTR];
    const int tid = threadIdx.x;
    const int m0 = blockIdx.y * 128, n0 = blockIdx.x * 128;
    const int wid = tid >> 5, lane = tid & 31;
    const int wm = wid >> 1, wn = wid & 1;
    const int g = lane >> 2, tig = lane & 3;
    const int am = tid >> 1, akq = (tid & 1) * 4;
    const int arow = m0 + am, bcol = n0 + am;
    const float* aptr = emb + (size_t)((arow < M) ? tok[arow] : 0) * ED;
    const bool aval = (arow < M);

    float4 acc[2][8];
#pragma unroll
    for (int i = 0; i < 2; i++)
#pragma unroll
        for (int j = 0; j < 8; j++) acc[i][j] = make_float4(0.f, 0.f, 0.f, 0.f);

    float ra[4], rb[4];
    const int nP = (ED + 7) / 8;  // 38

    auto loadP = [&](int k0) {
#pragma unroll
        for (int j = 0; j < 4; j++) {
            int kk = k0 + akq + j;
            ra[j] = (aval && kk < ED) ? aptr[kk] : 0.f;
            rb[j] = (bcol < GW && kk < ED) ? W[(size_t)bcol * ED + kk] : 0.f;
        }
    };
    auto storeP = [&](int b) {
#pragma unroll
        for (int j = 0; j < 4; j++) {
            As[b][akq + j][am] = ra[j];
            Bs[b][akq + j][am] = rb[j];
        }
    };

    loadP(0); storeP(0);
    __syncthreads();

    for (int p = 0; p < nP; p++) {
        if (p + 1 < nP) loadP((p + 1) * 8);
        const int b = p & 1;
        uint32_t af[2][4];
#pragma unroll
        for (int mf = 0; mf < 2; mf++) {
            int r0 = wm * 32 + mf * 16 + g;
            af[mf][0] = fu(As[b][tig][r0]);
            af[mf][1] = fu(As[b][tig][r0 + 8]);
            af[mf][2] = fu(As[b][tig + 4][r0]);
            af[mf][3] = fu(As[b][tig + 4][r0 + 8]);
        }
#pragma unroll
        for (int nf = 0; nf < 8; nf++) {
            int cn = wn * 64 + nf * 8 + g;
            uint32_t b0 = fu(Bs[b][tig][cn]);
            uint32_t b1 = fu(Bs[b][tig + 4][cn]);
            mma8(acc[0][nf], af[0][0], af[0][1], af[0][2], af[0][3], b0, b1);
            mma8(acc[1][nf], af[1][0], af[1][1], af[1][2], af[1][3], b0, b1);
        }
        if (p + 1 < nP) { storeP((p + 1) & 1); __syncthreads(); }
    }

#pragma unroll
    for (int mf = 0; mf < 2; mf++) {
        int r0 = m0 + wm * 32 + mf * 16 + g;
        int r1 = r0 + 8;
#pragma unroll
        for (int nf = 0; nf < 8; nf++) {
            int cc = n0 + wn * 64 + nf * 8 + tig * 2;
            float4 c = acc[mf][nf];
            float bx = (cc < GW) ? (b1[cc] + b2[cc]) : 0.f;
            float by = (cc + 1 < GW) ? (b1[cc + 1] + b2[cc + 1]) : 0.f;
            if (r0 < M) {
                if (cc < GW)     G[(size_t)r0 * GW + cc]     = c.x + bx;
                if (cc + 1 < GW) G[(size_t)r0 * GW + cc + 1] = c.y + by;
            }
            if (r1 < M) {
                if (cc < GW)     G[(size_t)r1 * GW + cc]     = c.z + bx;
                if (cc + 1 < GW) G[(size_t)r1 * GW + cc + 1] = c.w + by;
            }
        }
    }
}

// ---------------- fused LSTM recurrence step v6 (unchanged, proven) -------------
__device__ __forceinline__ float sigm(float x) { return 1.f / (1.f + expf(-x)); }

__global__ void __launch_bounds__(128)
lstm_step(const float* __restrict__ WhhF, const float* __restrict__ WhhB,
          int t, int Lcur, int isq) {
    const int tid = threadIdx.x;
    const int tx = tid & 31;
    const int ty = tid >> 5;
    const int ub = blockIdx.x, rbk = blockIdx.y, dir = blockIdx.z;
    const int u0 = ub * 32, n0 = rbk * ROWS;

    const float* __restrict__ Whh = dir ? WhhB : WhhF;
    const float* __restrict__ G = isq ? (dir ? d_Gqb : d_Gqf)
                                      : (dir ? d_Gb : d_Gf);
    float* hbase = isq ? d_hq : d_h;
    float* cbuf = (isq ? d_cq : d_c) + dir * (NB * HD);
    const float* hp = hbase + (dir * 2 + (t & 1)) * (NB * HD);
    float* hn = hbase + (dir * 2 + ((t + 1) & 1)) * (NB * HD);
    float* Hc = isq ? d_HcatQ : d_Hcat;
    const int tpos = dir ? (Lcur - 1 - t) : t;

    __shared__ __align__(16) float h_s[ROWS][300];
    __shared__ __align__(16) float Ws[2][20][128];
    float* gs = &Ws[1][0][0];

    const int gate = tx >> 3;
    const int un = u0 + (tx & 7) * 4;
    const bool uval = (un < HD);
    float acc[5][4];
#pragma unroll
    for (int j = 0; j < 5; j++) {
        int r = ty + 4 * j, n = n0 + r;
        if (uval && r < ROWS && n < NB) {
            float4 v = *(const float4*)(G + ((size_t)n * Lcur + tpos) * GW
                                          + gate * HD + un);
            acc[j][0] = v.x; acc[j][1] = v.y; acc[j][2] = v.z; acc[j][3] = v.w;
        } else {
            acc[j][0] = acc[j][1] = acc[j][2] = acc[j][3] = 0.f;
        }
    }

    float4 hreg[12];
#pragma unroll
    for (int q = 0; q < 12; q++) {
        int i = tid + q * 128;
        if (i < ROWS * 75) {
            int r = i / 75, c = i - r * 75;
            int n = n0 + r; if (n >= NB) n = NB - 1;
            hreg[q] = *((const float4*)(hp + (size_t)n * HD) + c);
        }
    }
#pragma unroll
    for (int q = 0; q < 12; q++) {
        int i = tid + q * 128;
        if (i < ROWS * 75) {
            int r = i / 75, c = i - r * 75;
            *((float4*)&h_s[r][0] + c) = hreg[q];
        }
    }

    const int lrow = (tid >> 5) * HD + u0 + (tid & 31);
    const bool lval = (u0 + (tid & 31)) < HD;
    float4 pre[5];

    if (lval) {
        const float* src = Whh + (size_t)lrow * HD;
#pragma unroll
        for (int q = 0; q < 5; q++) pre[q] = ((const float4*)src)[q];
#pragma unroll
        for (int q = 0; q < 5; q++) {
            Ws[0][q * 4 + 0][tid] = pre[q].x;
            Ws[0][q * 4 + 1][tid] = pre[q].y;
            Ws[0][q * 4 + 2][tid] = pre[q].z;
            Ws[0][q * 4 + 3][tid] = pre[q].w;
        }
    } else {
#pragma unroll
        for (int kk = 0; kk < 20; kk++) Ws[0][kk][tid] = 0.f;
    }
    __syncthreads();

    for (int p = 0; p < 15; p++) {
        if (p + 1 < 15 && lval) {
            const float* src = Whh + (size_t)lrow * HD + (p + 1) * 20;
#pragma unroll
            for (int q = 0; q < 5; q++) pre[q] = ((const float4*)src)[q];
        }
        const int b = p & 1, k0 = p * 20;
#pragma unroll
        for (int kk = 0; kk < 20; kk++) {
            float4 w = *(const float4*)&Ws[b][kk][tx * 4];
            float h0 = h_s[ty][k0 + kk];
            float h1 = h_s[ty + 4][k0 + kk];
            float h2 = h_s[ty + 8][k0 + kk];
            float h3 = h_s[ty + 12][k0 + kk];
            float h4 = (ty < 3) ? h_s[ty + 16][k0 + kk] : 0.f;
            acc[0][0] += h0 * w.x; acc[0][1] += h0 * w.y;
            acc[0][2] += h0 * w.z; acc[0][3] += h0 * w.w;
            acc[1][0] += h1 * w.x; acc[1][1] += h1 * w.y;
            acc[1][2] += h1 * w.z; acc[1][3] += h1 * w.w;
            acc[2][0] += h2 * w.x; acc[2][1] += h2 * w.y;
            acc[2][2] += h2 * w.z; acc[2][3] += h2 * w.w;
            acc[3][0] += h3 * w.x; acc[3][1] += h3 * w.y;
            acc[3][2] += h3 * w.z; acc[3][3] += h3 * w.w;
            acc[4][0] += h4 * w.x; acc[4][1] += h4 * w.y;
            acc[4][2] += h4 * w.z; acc[4][3] += h4 * w.w;
        }
        if (p + 1 < 15) {
            const int nb = (p + 1) & 1;
            if (lval) {
#pragma unroll
                for (int q = 0; q < 5; q++) {
                    Ws[nb][q * 4 + 0][tid] = pre[q].x;
                    Ws[nb][q * 4 + 1][tid] = pre[q].y;
                    Ws[nb][q * 4 + 2][tid] = pre[q].z;
                    Ws[nb][q * 4 + 3][tid] = pre[q].w;
                }
            } else {
#pragma unroll
                for (int kk = 0; kk < 20; kk++) Ws[nb][kk][tid] = 0.f;
            }
            __syncthreads();
        }
    }

#pragma unroll
    for (int j = 0; j < 5; j++) {
        int r = ty + 4 * j;
        if (r < ROWS)
            *(float4*)&gs[r * 128 + tx * 4] = make_float4(acc[j][0], acc[j][1],
                                                          acc[j][2], acc[j][3]);
    }
    __syncthreads();

    for (int p = tid; p < ROWS * 32; p += 128) {
        int ulane = p & 31, r = p >> 5;
        int u = u0 + ulane, n = n0 + r;
        if (u < HD && n < NB) {
            float gi = gs[r * 128 + ulane];
            float gf = gs[r * 128 + 32 + ulane];
            float gg = gs[r * 128 + 64 + ulane];
            float go = gs[r * 128 + 96 + ulane];
            float cold = cbuf[n * HD + u];
            float cn = sigm(gf) * cold + sigm(gi) * tanhf(gg);
            float hv = sigm(go) * tanhf(cn);
            cbuf[n * HD + u] = cn;
            hn[n * HD + u] = hv;
            Hc[((size_t)n * Lcur + tpos) * (2 * HD) + dir * HD + u] = hv;
        }
    }
}

// ---------------- attention dot: s[m] = dot(X[m,:], av) ----------------
__global__ void att_dot(const float* __restrict__ X, const float* __restrict__ av,
                        float* __restrict__ out, int M) {
    int w = (blockIdx.x * blockDim.x + threadIdx.x) >> 5;
    int lane = threadIdx.x & 31;
    if (w >= M) return;
    const float* x = X + (size_t)w * HD;
    float a = 0.f;
    for (int d = lane; d < HD; d += 32) a += x[d] * av[d];
#pragma unroll
    for (int o = 16; o; o >>= 1) a += __shfl_down_sync(0xffffffffu, a, o);
    if (lane == 0) out[w] = a;
}

// ---------------- query softmax pool ----------------
__global__ void qpool_k() {
    int n = blockIdx.x, tid = threadIdx.x;
    __shared__ float sc[QL];
    if (tid < QL) sc[tid] = d_sq[n * QL + tid];
    __syncthreads();
    float mx = -1e30f;
#pragma unroll
    for (int l = 0; l < QL; l++) mx = fmaxf(mx, sc[l]);
    float e[QL], sum = 0.f;
#pragma unroll
    for (int l = 0; l < QL; l++) { e[l] = expf(sc[l] - mx); sum += e[l]; }
    float inv = 1.f / sum;
    for (int d = tid; d < HD; d += 128) {
        float a = 0.f;
#pragma unroll
        for (int l = 0; l < QL; l++) a += e[l] * d_qenc[(n * QL + l) * HD + d];
        d_qv[n * HD + d] = a * inv;
    }
}

// ---------------- normalize query ----------------
__global__ void qnorm_k() {
    int n = blockIdx.x, tid = threadIdx.x;
    __shared__ float red[128];
    float ss = 0.f;
    for (int d = tid; d < HD; d += 128) { float v = d_qp[n * HD + d]; ss += v * v; }
    red[tid] = ss;
    __syncthreads();
    for (int s = 64; s; s >>= 1) { if (tid < s) red[tid] += red[tid + s]; __syncthreads(); }
    float inv = 1.f / fmaxf(sqrtf(red[0]), EPSN);
    for (int d = tid; d < HD; d += 128) d_qn[n * HD + d] = d_qp[n * HD + d] * inv;
}

// ---------------- final: sliding-window combos + cosines + mix ----------------
__global__ void final_k(const float* __restrict__ sw, const float* __restrict__ P,
                        float* __restrict__ out) {
    int w = (blockIdx.x * blockDim.x + threadIdx.x) >> 5;
    int lane = threadIdx.x & 31;
    if (w >= MS) return;
    int n = w >> 8, l = w & 255;
    int ln = (l + 1 < SL) ? l + 1 : SL - 1;
    int lp = (l > 0) ? l - 1 : 0;
    float sl = d_s[n * SL + l];
    float sn = d_s[n * SL + ln];
    float sp = d_s[n * SL + lp];
    float m1 = fmaxf(sl, sn);
    float e0 = expf(sl - m1), e1 = expf(sn - m1);
    float wf0 = e0 / (e0 + e1), wf1 = 1.f - wf0;
    float m2 = fmaxf(sp, sl);
    float f0 = expf(sp - m2), f1 = expf(sl - m2);
    float wb0 = f0 / (f0 + f1), wb1 = 1.f - wb0;

    const float* Pl = P + (size_t)(n * SL + l) * HD;
    const float* Pn = P + (size_t)(n * SL + ln) * HD;
    const float* Pp = P + (size_t)(n * SL + lp) * HD;
    const float* q = d_qn + n * HD;

    float dpq = 0.f, dpp = 0.f, duq = 0.f, duu = 0.f, dvq = 0.f, dvv = 0.f;
    for (int d = lane; d < HD; d += 32) {
        float p = Pl[d], pn = Pn[d], pp = Pp[d], qd = q[d];
        float u = wf0 * p + wf1 * pn;
        float v = wb0 * pp + wb1 * p;
        dpq += p * qd; dpp += p * p;
        duq += u * qd; duu += u * u;
        dvq += v * qd; dvv += v * v;
    }
#pragma unroll
    for (int o = 16; o; o >>= 1) {
        dpq += __shfl_down_sync(0xffffffffu, dpq, o);
        dpp += __shfl_down_sync(0xffffffffu, dpp, o);
        duq += __shfl_down_sync(0xffffffffu, duq, o);
        duu += __shfl_down_sync(0xffffffffu, duu, o);
        dvq += __shfl_down_sync(0xffffffffu, dvq, o);
        dvv += __shfl_down_sync(0xffffffffu, dvv, o);
    }
    if (lane == 0) {
        float c1 = dpq / fmaxf(sqrtf(dpp), EPSN);
        float c2 = duq / fmaxf(sqrtf(duu), EPSN);
        float c3 = dvq / fmaxf(sqrtf(dvv), EPSN);
        out[w] = c1 * sw[0] + c2 * sw[1] + c3 * sw[2];
    }
}

// ---------------- launch ----------------
extern "C" void kernel_launch(void* const* d_in, const int* in_sizes, int n_in,
                              void* d_out, int out_size) {
    const int*   seqs = (const int*)d_in[0];
    const int*   quer = (const int*)d_in[1];
    const float* emb  = (const float*)d_in[2];
    const float* WihF = (const float*)d_in[3];
    const float* WhhF = (const float*)d_in[4];
    const float* bihF = (const float*)d_in[5];
    const float* bhhF = (const float*)d_in[6];
    const float* WihB = (const float*)d_in[7];
    const float* WhhB = (const float*)d_in[8];
    const float* bihB = (const float*)d_in[9];
    const float* bhhB = (const float*)d_in[10];
    const float* Wc   = (const float*)d_in[11];
    const float* bc   = (const float*)d_in[12];
    const float* Wa   = (const float*)d_in[13];
    const float* ba   = (const float*)d_in[14];
    const float* av   = (const float*)d_in[15];
    const float* Wf   = (const float*)d_in[16];
    const float* sw   = (const float*)d_in[17];

    void* p;
    cudaGetSymbolAddress(&p, d_Gf);    float* pGf    = (float*)p;
    cudaGetSymbolAddress(&p, d_Gb);    float* pGb    = (float*)p;
    cudaGetSymbolAddress(&p, d_Gqf);   float* pGqf   = (float*)p;
    cudaGetSymbolAddress(&p, d_Gqb);   float* pGqb   = (float*)p;
    cudaGetSymbolAddress(&p, d_Hcat);  float* pHcat  = (float*)p;
    cudaGetSymbolAddress(&p, d_HcatQ); float* pHcatQ = (float*)p;
    cudaGetSymbolAddress(&p, d_hs);    float* phs    = (float*)p;
    cudaGetSymbolAddress(&p, d_qenc);  float* pqenc  = (float*)p;
    cudaGetSymbolAddress(&p, d_tmp);   float* ptmp   = (float*)p;  // doubles as P
    cudaGetSymbolAddress(&p, d_tmpq);  float* ptmpq  = (float*)p;
    cudaGetSymbolAddress(&p, d_s);     float* ps     = (float*)p;
    cudaGetSymbolAddress(&p, d_sq);    float* psq    = (float*)p;
    cudaGetSymbolAddress(&p, d_qv);    float* pqv    = (float*)p;
    cudaGetSymbolAddress(&p, d_qp);    float* pqp    = (float*)p;

    init_state<<<600, 256>>>();

    // input projections (gather + tf32 GEMM + both biases)
    dim3 gp(10, 256);
    mma_proj<<<gp, 256>>>(seqs, emb, WihF, bihF, bhhF, pGf, MS);
    mma_proj<<<gp, 256>>>(seqs, emb, WihB, bihB, bhhB, pGb, MS);
    dim3 gpq(10, 8);
    mma_proj<<<gpq, 256>>>(quer, emb, WihF, bihF, bhhF, pGqf, MQ);
    mma_proj<<<gpq, 256>>>(quer, emb, WihB, bihB, bhhB, pGqb, MQ);

    // recurrences: one launch per timestep, both dirs; 140 CTAs = single wave
    dim3 gl(10, RBL, 2);
    for (int t = 0; t < SL; t++) lstm_step<<<gl, 128>>>(WhhF, WhhB, t, SL, 0);
    for (int t = 0; t < QL; t++) lstm_step<<<gl, 128>>>(WhhF, WhhB, t, QL, 1);

    // combine directions: hs = Hcat @ Wc^T + bc
    mma_gemm<<<dim3(3, 256), 256>>>(pHcat, Wc, bc, phs, MS, HD, 2 * HD, 1, 0);
    mma_gemm<<<dim3(3, 8), 256>>>(pHcatQ, Wc, bc, pqenc, MQ, HD, 2 * HD, 1, 0);

    // attention logits: tanh(X @ Wa^T + ba) . att_vec
    mma_gemm<<<dim3(3, 256), 256>>>(phs, Wa, ba, ptmp, MS, HD, HD, 1, 1);
    mma_gemm<<<dim3(3, 8), 256>>>(pqenc, Wa, ba, ptmpq, MQ, HD, HD, 1, 1);
    att_dot<<<MS / 8, 256>>>(ptmp, av, ps, MS);
    att_dot<<<MQ / 8, 256>>>(ptmpq, av, psq, MQ);

    // pooled, projected, normalized query
    qpool_k<<<NB, 128>>>();
    mma_gemm<<<dim3(3, 1), 256>>>(pqv, Wf, nullptr, pqp, NB, HD, HD, 0, 0);
    qnorm_k<<<NB, 128>>>();

    // P = hs @ Wf  (fwd/bwd combos are linear in hs, so one projection suffices)
    mma_gemm<<<dim3(3, 256), 256>>>(phs, Wf, nullptr, ptmp, MS, HD, HD, 0, 0);

    final_k<<<MS / 8, 256>>>(sw, ptmp, (float*)d_out);
}